// round 7
// baseline (speedup 1.0000x reference)
#include <cuda_runtime.h>
#include <cuda_bf16.h>
#include <cuda_fp16.h>

#define N_TOK 8192
#define DMODEL 1024
#define DFF 4096
#define NEXP 8
#define NPAIR (N_TOK * 2)
#define EPSF 1.1920928955078125e-07f
#define STAGE 65536u
#define SMEM_BF (2 * 65536)
#define STAGEH 49152u
#define SMEM_F16 (2 * 49152)
typedef __nv_bfloat16 bf;
typedef __nv_bfloat162 bf2;
typedef long long ll;

__device__ float g_h[(size_t)N_TOK * DMODEL];
__device__ float g_Oe[(size_t)NPAIR * DMODEL];
__device__ bf g_sH[(size_t)N_TOK*DMODEL], g_sL[(size_t)N_TOK*DMODEL];
__device__ bf g_yH[(size_t)N_TOK*DMODEL], g_yL[(size_t)N_TOK*DMODEL];
__device__ bf g_WinH[(size_t)DMODEL*DMODEL], g_WinL[(size_t)DMODEL*DMODEL];
__device__ bf g_WoH[(size_t)DMODEL*DMODEL], g_WoL[(size_t)DMODEL*DMODEL];
__device__ __half g_hHf[(size_t)N_TOK*DMODEL], g_hLf[(size_t)N_TOK*DMODEL];
__device__ __half g_THf[(size_t)NPAIR*DFF], g_TLf[(size_t)NPAIR*DFF];
__device__ __half g_WgF[(size_t)NEXP*DFF*DMODEL];
__device__ __half g_WuF[(size_t)NEXP*DFF*DMODEL];
__device__ __half g_WdF[(size_t)NEXP*DMODEL*DFF];
__device__ int g_cnt[NEXP], g_off[NEXP+1], g_cur[NEXP];
__device__ int g_pairtok[NPAIR], g_slotof[NPAIR], g_topidx[NPAIR];
__device__ float g_topgate[NPAIR];

__device__ __forceinline__ unsigned su32(const void* p){
    unsigned a; asm("{ .reg .u64 t; cvta.to.shared.u64 t, %1; cvt.u32.u64 %0, t; }":"=r"(a):"l"(p)); return a;
}
__device__ __forceinline__ void cp16(unsigned d, const void* s){
    asm volatile("cp.async.cg.shared.global [%0], [%1], 16;"::"r"(d),"l"(s));
}
__device__ __forceinline__ unsigned swz(unsigned off){ return off ^ ((off>>3)&0x70u); }
__device__ __forceinline__ void ldsm4(unsigned* r, unsigned a){
    asm volatile("ldmatrix.sync.aligned.m8n8.x4.shared.b16 {%0,%1,%2,%3}, [%4];"
        :"=r"(r[0]),"=r"(r[1]),"=r"(r[2]),"=r"(r[3]):"r"(a));
}
__device__ __forceinline__ void ldsm2(unsigned* r, unsigned a){
    asm volatile("ldmatrix.sync.aligned.m8n8.x2.shared.b16 {%0,%1}, [%2];"
        :"=r"(r[0]),"=r"(r[1]):"r"(a));
}
__device__ __forceinline__ void mma_bf(float* c, const unsigned* a, unsigned b0, unsigned b1){
    asm volatile("mma.sync.aligned.m16n8k16.row.col.f32.bf16.bf16.f32 "
        "{%0,%1,%2,%3},{%4,%5,%6,%7},{%8,%9},{%0,%1,%2,%3};"
        :"+f"(c[0]),"+f"(c[1]),"+f"(c[2]),"+f"(c[3])
        :"r"(a[0]),"r"(a[1]),"r"(a[2]),"r"(a[3]),"r"(b0),"r"(b1));
}
__device__ __forceinline__ void mma_hf(float* c, const unsigned* a, unsigned b0, unsigned b1){
    asm volatile("mma.sync.aligned.m16n8k16.row.col.f32.f16.f16.f32 "
        "{%0,%1,%2,%3},{%4,%5,%6,%7},{%8,%9},{%0,%1,%2,%3};"
        :"+f"(c[0]),"+f"(c[1]),"+f"(c[2]),"+f"(c[3])
        :"r"(a[0]),"r"(a[1]),"r"(a[2]),"r"(a[3]),"r"(b0),"r"(b1));
}
__device__ __forceinline__ void split2(float x, bf& h, bf& l){
    h = __float2bfloat16(x); l = __float2bfloat16(x - __bfloat162float(h));
}
__device__ __forceinline__ void split2h(float x, __half& h, __half& l){
    h = __float2half_rn(x); l = __float2half_rn(x - __half2float(h));
}

__global__ void init_counts(){ if (threadIdx.x < NEXP) g_cnt[threadIdx.x] = 0; }
__global__ void scan_offsets(){
    if (threadIdx.x == 0){ int s=0; for(int e=0;e<NEXP;e++){ g_off[e]=s; s+=g_cnt[e]; } g_off[NEXP]=s; }
    if (threadIdx.x < NEXP) g_cur[threadIdx.x] = 0;
}
__global__ void scatter_pairs(){
    int t = blockIdx.x*blockDim.x + threadIdx.x; if (t >= N_TOK) return;
    for (int k=0;k<2;k++){
        int e = g_topidx[2*t+k];
        int slot = g_off[e] + atomicAdd(&g_cur[e],1);
        g_pairtok[slot] = t; g_slotof[2*t+k] = slot;
    }
}
__global__ void convert_hilo(const float* __restrict__ x, bf* __restrict__ h, bf* __restrict__ l, int n4){
    int i = blockIdx.x*blockDim.x + threadIdx.x; if (i >= n4) return;
    float4 v = ((const float4*)x)[i];
    bf2 p0,p1,q0,q1;
    split2(v.x,p0.x,q0.x); split2(v.y,p0.y,q0.y); split2(v.z,p1.x,q1.x); split2(v.w,p1.y,q1.y);
    ((bf2*)h)[2*i]=p0; ((bf2*)h)[2*i+1]=p1; ((bf2*)l)[2*i]=q0; ((bf2*)l)[2*i+1]=q1;
}
__global__ void convert_f16(const float* __restrict__ x, __half* __restrict__ o, int n4){
    int i = blockIdx.x*blockDim.x + threadIdx.x; if (i >= n4) return;
    float4 v = ((const float4*)x)[i];
    __half2 p0, p1;
    p0.x = __float2half_rn(v.x); p0.y = __float2half_rn(v.y);
    p1.x = __float2half_rn(v.z); p1.y = __float2half_rn(v.w);
    ((__half2*)o)[2*i]=p0; ((__half2*)o)[2*i+1]=p1;
}
__global__ void rmsnorm_f16(const float* __restrict__ X, const float* __restrict__ w,
                            float* __restrict__ Y, __half* __restrict__ YH, __half* __restrict__ YL){
    int row = blockIdx.x, tid = threadIdx.x;
    float4 v = ((const float4*)(X + (ll)row*DMODEL))[tid];
    float ss = v.x*v.x+v.y*v.y+v.z*v.z+v.w*v.w;
    __shared__ float red[8];
    for (int o=16;o;o>>=1) ss += __shfl_xor_sync(~0u, ss, o);
    if ((tid&31)==0) red[tid>>5]=ss;
    __syncthreads();
    float tot = red[0]+red[1]+red[2]+red[3]+red[4]+red[5]+red[6]+red[7];
    float r = rsqrtf(tot*(1.0f/DMODEL)+EPSF);
    float4 wv = ((const float4*)w)[tid];
    float4 o4 = make_float4(v.x*r*wv.x, v.y*r*wv.y, v.z*r*wv.z, v.w*r*wv.w);
    ((float4*)(Y + (ll)row*DMODEL))[tid] = o4;
    __half2 p0,p1,q0,q1;
    split2h(o4.x,p0.x,q0.x); split2h(o4.y,p0.y,q0.y); split2h(o4.z,p1.x,q1.x); split2h(o4.w,p1.y,q1.y);
    __half2* ph=(__half2*)(YH+(ll)row*DMODEL); __half2* pl=(__half2*)(YL+(ll)row*DMODEL);
    ph[2*tid]=p0; ph[2*tid+1]=p1; pl[2*tid]=q0; pl[2*tid+1]=q1;
}
__global__ void router_kernel(const float* __restrict__ h, const float* __restrict__ Wr, const float* __restrict__ bias){
    int warp = (blockIdx.x*blockDim.x+threadIdx.x)>>5, lane = threadIdx.x&31;
    if (warp >= N_TOK) return;
    const float* hr = h + (ll)warp*DMODEL;
    float acc[NEXP];
    #pragma unroll
    for (int e=0;e<NEXP;e++) acc[e]=0.f;
    for (int d=lane; d<DMODEL; d+=32){
        float hv = hr[d];
        #pragma unroll
        for (int e=0;e<NEXP;e++) acc[e] += hv*Wr[e*DMODEL+d];
    }
    #pragma unroll
    for (int e=0;e<NEXP;e++)
        for (int o=16;o;o>>=1) acc[e] += __shfl_xor_sync(~0u, acc[e], o);
    if (lane==0){
        float b0=-1e30f,b1=-1e30f; int i0=0,i1=0;
        #pragma unroll
        for (int e=0;e<NEXP;e++){
            float v = acc[e]+bias[e];
            if (v>b0){ b1=b0;i1=i0;b0=v;i0=e; } else if (v>b1){ b1=v;i1=e; }
        }
        float m=fmaxf(acc[i0],acc[i1]);
        float e0=expf(acc[i0]-m), e1=expf(acc[i1]-m), inv=1.f/(e0+e1);
        g_topidx[2*warp]=i0; g_topidx[2*warp+1]=i1;
        g_topgate[2*warp]=e0*inv; g_topgate[2*warp+1]=e1*inv;
        atomicAdd(&g_cnt[i0],1); atomicAdd(&g_cnt[i1],1);
    }
}

// ---------- bf16 3-pass GEMM (R4-proven, non-dual path), 128x128 tile ----------
__global__ __launch_bounds__(256) void mm_bf(
    const bf* __restrict__ Ah, const bf* __restrict__ Al,
    const bf* __restrict__ B0h, const bf* __restrict__ B0l,
    float* __restrict__ C, int Mdense, int K, int Ncols)
{
    extern __shared__ char dsm[];
    int Mloc = Mdense;
    int bm = blockIdx.x*128; if (bm >= Mloc) return;
    int bn = blockIdx.y*128;
    unsigned sb = su32(dsm);
    int tid = threadIdx.x;
    int aslot = tid&7, arow0 = tid>>3;
    int ga[4];
    #pragma unroll
    for (int j=0;j<4;j++){
        int lr = bm + arow0 + 32*j; if (lr > Mloc-1) lr = Mloc-1;
        ga[j] = lr;
    }
    int w = tid>>5, lane = tid&31;
    int wm = (w>>2)*64;
    int wn = (w&3)*32;
    float acc[4][4][4];
    #pragma unroll
    for (int i=0;i<4;i++)
        #pragma unroll
        for (int j=0;j<4;j++)
            #pragma unroll
            for (int q=0;q<4;q++) acc[i][j][q] = 0.f;

    int total = K>>6;
    for (int c = -1; c < total; ++c){
        int nl = c+1;
        if (nl < total){
            unsigned base = sb + (unsigned)(nl&1)*STAGE;
            int ke = nl*64 + aslot*8;
            #pragma unroll
            for (int j=0;j<4;j++){
                unsigned sw = swz((unsigned)((arow0+32*j)*128 + aslot*16));
                cp16(base+sw,        Ah + (ll)ga[j]*K + ke);
                cp16(base+16384u+sw, Al + (ll)ga[j]*K + ke);
                int br = bn + arow0 + 32*j;
                cp16(base+32768u+sw, B0h + (ll)br*K + ke);
                cp16(base+49152u+sw, B0l + (ll)br*K + ke);
            }
            asm volatile("cp.async.commit_group;":::"memory");
        }
        if (c < 0) continue;
        if (nl < total) asm volatile("cp.async.wait_group 1;":::"memory");
        else            asm volatile("cp.async.wait_group 0;":::"memory");
        __syncthreads();

        unsigned base = sb + (unsigned)(c&1)*STAGE;
        int lrow8 = ((lane>>3)&1)*8 + (lane&7);
        #pragma unroll
        for (int ks=0; ks<4; ks++){
            int kb = ks*32 + (lane>>4)*16;
            unsigned BH[2][4], BL[2][4];
            #pragma unroll
            for (int t=0;t<2;t++){
                unsigned sw = swz((unsigned)((wn + t*16 + lrow8)*128 + kb));
                ldsm4(BH[t], base + 32768u + sw);
                ldsm4(BL[t], base + 49152u + sw);
            }
            #pragma unroll
            for (int tm=0;tm<4;tm++){
                unsigned ah[4], al[4];
                unsigned asw = swz((unsigned)((wm + tm*16 + lrow8)*128 + kb));
                ldsm4(ah, base + asw);
                ldsm4(al, base + 16384u + asw);
                #pragma unroll
                for (int t=0;t<2;t++){
                    int j0=2*t, j1=2*t+1;
                    mma_bf(acc[tm][j0], ah, BH[t][0], BH[t][2]);
                    mma_bf(acc[tm][j0], ah, BL[t][0], BL[t][2]);
                    mma_bf(acc[tm][j0], al, BH[t][0], BH[t][2]);
                    mma_bf(acc[tm][j1], ah, BH[t][1], BH[t][3]);
                    mma_bf(acc[tm][j1], ah, BL[t][1], BL[t][3]);
                    mma_bf(acc[tm][j1], al, BH[t][1], BH[t][3]);
                }
            }
        }
        __syncthreads();
    }
    #pragma unroll
    for (int tm=0;tm<4;tm++){
        int r = bm + wm + tm*16 + (lane>>2);
        #pragma unroll
        for (int j=0;j<4;j++){
            float* cc = acc[tm][j];
            int col = bn + wn + j*8 + (lane&3)*2;
            if (r < Mloc)
                *(float2*)(C + (ll)r*Ncols + col) = make_float2(cc[0],cc[1]);
            if (r+8 < Mloc)
                *(float2*)(C + (ll)(r+8)*Ncols + col) = make_float2(cc[2],cc[3]);
        }
    }
}

// ---------- fp16 2-pass grouped expert GEMM: C = (Ah+Al) * Bh^T ----------
// DUAL=1 (gateup): B = 64 gate rows + 64 up rows, epilogue silu(g)*u -> half hi/lo.
// DUAL=0 (down):   B = 128 rows of Wd, epilogue fp32 C.
// Stage: Ah 16K @0, Al 16K @16K, Bh 16K @32K = 48KB; 2 stages; 2 CTAs/SM.
template<int DUAL>
__global__ __launch_bounds__(256, 2) void mm_f16(
    const __half* __restrict__ Ah, const __half* __restrict__ Al,
    const __half* __restrict__ B0, const __half* __restrict__ B1,
    float* __restrict__ C, __half* __restrict__ TH, __half* __restrict__ TL,
    int K, int Ncols,
    const int* __restrict__ d_off, const int* __restrict__ pairtok, ll strideB)
{
    extern __shared__ char dsm[];
    int e = blockIdx.z;
    int rowBase = d_off[e], Mloc = d_off[e+1]-rowBase;
    const __half* b0 = B0 + (ll)e*strideB;
    const __half* b1 = DUAL ? (B1 + (ll)e*strideB) : nullptr;
    int bm = blockIdx.x*128; if (bm >= Mloc) return;
    int bn = blockIdx.y*(DUAL?64:128);

    unsigned sb = su32(dsm);
    int tid = threadIdx.x;
    int aslot = tid&7, arow0 = tid>>3;
    int ga[4];
    #pragma unroll
    for (int j=0;j<4;j++){
        int lr = bm + arow0 + 32*j; if (lr > Mloc-1) lr = Mloc-1;
        ga[j] = DUAL ? pairtok[rowBase+lr] : (rowBase+lr);
    }
    int w = tid>>5, lane = tid&31;
    int wm = DUAL ? (w>>1)*32 : (w>>2)*64;
    int wn = (DUAL ? (w&1) : (w&3))*32;
    constexpr int MT = DUAL ? 2 : 4;
    constexpr int NB = DUAL ? 4 : 2;

    float acc[4][4][4];   // dual: [0..1]=gate, [2..3]=up
    #pragma unroll
    for (int i=0;i<4;i++)
        #pragma unroll
        for (int j=0;j<4;j++)
            #pragma unroll
            for (int q=0;q<4;q++) acc[i][j][q] = 0.f;

    int total = K>>6;
    for (int c = -1; c < total; ++c){
        int nl = c+1;
        if (nl < total){
            unsigned base = sb + (unsigned)(nl&1)*STAGEH;
            int ke = nl*64 + aslot*8;
            #pragma unroll
            for (int j=0;j<4;j++){
                int r = arow0 + 32*j;
                unsigned sw = swz((unsigned)(r*128 + aslot*16));
                cp16(base+sw,        Ah + (ll)ga[j]*K + ke);
                cp16(base+16384u+sw, Al + (ll)ga[j]*K + ke);
                const __half* bp; int br;
                if (DUAL && r >= 64){ bp = b1; br = bn + r - 64; }
                else                { bp = b0; br = bn + r; }
                cp16(base+32768u+sw, bp + (ll)br*K + ke);
            }
            asm volatile("cp.async.commit_group;":::"memory");
        }
        if (c < 0) continue;
        if (nl < total) asm volatile("cp.async.wait_group 1;":::"memory");
        else            asm volatile("cp.async.wait_group 0;":::"memory");
        __syncthreads();

        unsigned base = sb + (unsigned)(c&1)*STAGEH;
        int lrow8 = ((lane>>3)&1)*8 + (lane&7);
        #pragma unroll
        for (int ks=0; ks<4; ks++){
            int kb = ks*32 + (lane>>4)*16;
            unsigned BH[NB][4];
            #pragma unroll
            for (int t=0;t<NB;t++){
                int nb = (DUAL && t>=2) ? (64 + wn + (t-2)*16) : (wn + t*16);
                ldsm4(BH[t], base + 32768u + swz((unsigned)((nb + lrow8)*128 + kb)));
            }
            #pragma unroll
            for (int tm=0;tm<MT;tm++){
                unsigned ah[4], al[4];
                unsigned asw = swz((unsigned)((wm + tm*16 + lrow8)*128 + kb));
                ldsm4(ah, base + asw);
                ldsm4(al, base + 16384u + asw);
                #pragma unroll
                for (int t=0;t<2;t++){
                    int j0=2*t, j1=2*t+1;
                    mma_hf(acc[tm][j0], ah, BH[t][0], BH[t][2]);
                    mma_hf(acc[tm][j0], al, BH[t][0], BH[t][2]);
                    mma_hf(acc[tm][j1], ah, BH[t][1], BH[t][3]);
                    mma_hf(acc[tm][j1], al, BH[t][1], BH[t][3]);
                    if (DUAL){
                        mma_hf(acc[2+tm][j0], ah, BH[2+t][0], BH[2+t][2]);
                        mma_hf(acc[2+tm][j0], al, BH[2+t][0], BH[2+t][2]);
                        mma_hf(acc[2+tm][j1], ah, BH[2+t][1], BH[2+t][3]);
                        mma_hf(acc[2+tm][j1], al, BH[2+t][1], BH[2+t][3]);
                    }
                }
            }
        }
        __syncthreads();
    }

    if (!DUAL){
        #pragma unroll
        for (int tm=0;tm<4;tm++){
            int r = bm + wm + tm*16 + (lane>>2);
            #pragma unroll
            for (int j=0;j<4;j++){
                float* cc = acc[tm][j];
                int col = bn + wn + j*8 + (lane&3)*2;
                if (r < Mloc)
                    *(float2*)(C + (ll)(rowBase+r)*Ncols + col) = make_float2(cc[0],cc[1]);
                if (r+8 < Mloc)
                    *(float2*)(C + (ll)(rowBase+r+8)*Ncols + col) = make_float2(cc[2],cc[3]);
            }
        }
    } else {
        #pragma unroll
        for (int tm=0;tm<2;tm++){
            int r = bm + wm + tm*16 + (lane>>2);
            #pragma unroll
            for (int j=0;j<4;j++){
                float* gg = acc[tm][j];
                float* uu = acc[2+tm][j];
                float v0 = gg[0]*uu[0]/(1.f+__expf(-gg[0]));
                float v1 = gg[1]*uu[1]/(1.f+__expf(-gg[1]));
                float v2 = gg[2]*uu[2]/(1.f+__expf(-gg[2]));
                float v3 = gg[3]*uu[3]/(1.f+__expf(-gg[3]));
                int col = bn + wn + j*8 + (lane&3)*2;
                __half2 h0,l0,h1,l1;
                split2h(v0,h0.x,l0.x); split2h(v1,h0.y,l0.y);
                split2h(v2,h1.x,l1.x); split2h(v3,h1.y,l1.y);
                if (r < Mloc){
                    *(__half2*)(TH + (ll)(rowBase+r)*Ncols + col) = h0;
                    *(__half2*)(TL + (ll)(rowBase+r)*Ncols + col) = l0;
                }
                if (r+8 < Mloc){
                    *(__half2*)(TH + (ll)(rowBase+r+8)*Ncols + col) = h1;
                    *(__half2*)(TL + (ll)(rowBase+r+8)*Ncols + col) = l1;
                }
            }
        }
    }
}

__global__ void combine_rows(const float* __restrict__ enorm, const float* __restrict__ outnorm){
    int t = blockIdx.x, tid = threadIdx.x;
    int s0=g_slotof[2*t], s1=g_slotof[2*t+1], e0=g_topidx[2*t], e1=g_topidx[2*t+1];
    float gg0=g_topgate[2*t], gg1=g_topgate[2*t+1];
    float4 a = ((const float4*)(g_Oe+(ll)s0*DMODEL))[tid];
    float4 b = ((const float4*)(g_Oe+(ll)s1*DMODEL))[tid];
    float ssa=a.x*a.x+a.y*a.y+a.z*a.z+a.w*a.w, ssb=b.x*b.x+b.y*b.y+b.z*b.z+b.w*b.w;
    __shared__ float rA[8],rB[8],rC[8];
    for (int o=16;o;o>>=1){ ssa+=__shfl_xor_sync(~0u,ssa,o); ssb+=__shfl_xor_sync(~0u,ssb,o); }
    if ((tid&31)==0){ rA[tid>>5]=ssa; rB[tid>>5]=ssb; }
    __syncthreads();
    float ta=rA[0]+rA[1]+rA[2]+rA[3]+rA[4]+rA[5]+rA[6]+rA[7];
    float tb=rB[0]+rB[1]+rB[2]+rB[3]+rB[4]+rB[5]+rB[6]+rB[7];
    float r0=rsqrtf(ta*(1.f/DMODEL)+EPSF)*gg0, r1=rsqrtf(tb*(1.f/DMODEL)+EPSF)*gg1;
    float4 w0=((const float4*)(enorm+(ll)e0*DMODEL))[tid];
    float4 w1=((const float4*)(enorm+(ll)e1*DMODEL))[tid];
    float4 c = make_float4(a.x*r0*w0.x+b.x*r1*w1.x, a.y*r0*w0.y+b.y*r1*w1.y,
                           a.z*r0*w0.z+b.z*r1*w1.z, a.w*r0*w0.w+b.w*r1*w1.w);
    float ssc=c.x*c.x+c.y*c.y+c.z*c.z+c.w*c.w;
    for (int o=16;o;o>>=1) ssc+=__shfl_xor_sync(~0u,ssc,o);
    if ((tid&31)==0) rC[tid>>5]=ssc;
    __syncthreads();
    float tc=rC[0]+rC[1]+rC[2]+rC[3]+rC[4]+rC[5]+rC[6]+rC[7];
    float rc=rsqrtf(tc*(1.f/DMODEL)+EPSF);
    float4 wo=((const float4*)outnorm)[tid];
    float4 o4=make_float4(c.x*rc*wo.x, c.y*rc*wo.y, c.z*rc*wo.z, c.w*rc*wo.w);
    bf2 p0,p1,q0,q1;
    split2(o4.x,p0.x,q0.x); split2(o4.y,p0.y,q0.y); split2(o4.z,p1.x,q1.x); split2(o4.w,p1.y,q1.y);
    bf2* ph=(bf2*)(g_yH+(ll)t*DMODEL); bf2* pl=(bf2*)(g_yL+(ll)t*DMODEL);
    ph[2*tid]=p0; ph[2*tid+1]=p1; pl[2*tid]=q0; pl[2*tid+1]=q1;
}

extern "C" void kernel_launch(void* const* d_in, const int* in_sizes, int n_in,
                              void* d_out, int out_size)
{
    const float* s          = (const float*)d_in[0];
    const float* W_in       = (const float*)d_in[1];
    const float* in_norm_w  = (const float*)d_in[2];
    const float* Wr         = (const float*)d_in[3];
    const float* expert_bias= (const float*)d_in[4];
    const float* Wg         = (const float*)d_in[5];
    const float* Wu         = (const float*)d_in[6];
    const float* Wd         = (const float*)d_in[7];
    const float* enorm_w    = (const float*)d_in[8];
    const float* out_norm_w = (const float*)d_in[9];
    const float* W_out      = (const float*)d_in[10];
    float* out = (float*)d_out;

    cudaFuncSetAttribute(mm_bf, cudaFuncAttributeMaxDynamicSharedMemorySize, SMEM_BF);
    cudaFuncSetAttribute(mm_f16<1>, cudaFuncAttributeMaxDynamicSharedMemorySize, SMEM_F16);
    cudaFuncSetAttribute(mm_f16<0>, cudaFuncAttributeMaxDynamicSharedMemorySize, SMEM_F16);

    void* p;
    #define SYM(v,T,sname) cudaGetSymbolAddress(&p,sname); T* v=(T*)p;
    SYM(h_ptr,float,g_h) SYM(Oe_ptr,float,g_Oe)
    SYM(sH,bf,g_sH) SYM(sL,bf,g_sL)
    SYM(yH,bf,g_yH) SYM(yL,bf,g_yL)
    SYM(WinH,bf,g_WinH) SYM(WinL,bf,g_WinL)
    SYM(WoH,bf,g_WoH) SYM(WoL,bf,g_WoL)
    SYM(hHf,__half,g_hHf) SYM(hLf,__half,g_hLf)
    SYM(THf,__half,g_THf) SYM(TLf,__half,g_TLf)
    SYM(WgF,__half,g_WgF) SYM(WuF,__half,g_WuF) SYM(WdF,__half,g_WdF)
    SYM(off_ptr,int,g_off) SYM(ptok,int,g_pairtok)
    #undef SYM

    init_counts<<<1,32>>>();
    int nW = DMODEL*DMODEL/4, nE = NEXP*DFF*DMODEL/4;
    convert_hilo<<<(N_TOK*DMODEL/4+255)/256,256>>>(s, sH, sL, N_TOK*DMODEL/4);
    convert_hilo<<<(nW+255)/256,256>>>(W_in, WinH, WinL, nW);
    convert_f16<<<(nE+255)/256,256>>>(Wg, WgF, nE);
    convert_f16<<<(nE+255)/256,256>>>(Wu, WuF, nE);
    convert_f16<<<(nE+255)/256,256>>>(Wd, WdF, nE);
    convert_hilo<<<(nW+255)/256,256>>>(W_out, WoH, WoL, nW);

    // h_pre = s @ W_in^T  (bf16 3-pass)
    mm_bf<<<dim3(N_TOK/128, DMODEL/128), 256, SMEM_BF>>>(
        sH, sL, WinH, WinL, h_ptr, N_TOK, DMODEL, DMODEL);
    rmsnorm_f16<<<N_TOK,256>>>(h_ptr, in_norm_w, h_ptr, hHf, hLf);
    router_kernel<<<(N_TOK*32)/256,256>>>(h_ptr, Wr, expert_bias);
    scan_offsets<<<1,32>>>();
    scatter_pairs<<<N_TOK/256,256>>>();

    // T = silu(h Wg^T) * (h Wu^T)  (fp16 2-pass, gathered, grouped, dual-B)
    mm_f16<1><<<dim3(NPAIR/128, DFF/64, NEXP), 256, SMEM_F16>>>(
        hHf, hLf, WgF, WuF, nullptr, THf, TLf,
        DMODEL, DFF, off_ptr, ptok, (ll)DFF*DMODEL);

    // Oe = T @ Wd^T  (fp16 2-pass, grouped)
    mm_f16<0><<<dim3(NPAIR/128, DMODEL/128, NEXP), 256, SMEM_F16>>>(
        THf, TLf, WdF, nullptr, Oe_ptr, nullptr, nullptr,
        DFF, DMODEL, off_ptr, nullptr, (ll)DMODEL*DFF);

    combine_rows<<<N_TOK,256>>>(enorm_w, out_norm_w);

    // out = y @ W_out^T  (bf16 3-pass)
    mm_bf<<<dim3(N_TOK/128, DMODEL/128), 256, SMEM_BF>>>(
        yH, yL, WoH, WoL, out, N_TOK, DMODEL, DMODEL);
}

// round 8
// speedup vs baseline: 1.0003x; 1.0003x over previous
#include <cuda_runtime.h>
#include <cuda_bf16.h>
#include <cuda_fp16.h>

#define N_TOK 8192
#define DMODEL 1024
#define DFF 4096
#define NEXP 8
#define NPAIR (N_TOK * 2)
#define EPSF 1.1920928955078125e-07f
#define STAGE 65536u
#define SMEM_BF (2 * 65536)
#define STAGEH 49152u
#define SMEM_F16 (2 * 49152)
typedef __nv_bfloat16 bf;
typedef __nv_bfloat162 bf2;
typedef long long ll;

__device__ float g_h[(size_t)N_TOK * DMODEL];
__device__ float g_Oe[(size_t)NPAIR * DMODEL];
__device__ bf g_sH[(size_t)N_TOK*DMODEL], g_sL[(size_t)N_TOK*DMODEL];
__device__ bf g_yH[(size_t)N_TOK*DMODEL], g_yL[(size_t)N_TOK*DMODEL];
__device__ bf g_WinH[(size_t)DMODEL*DMODEL], g_WinL[(size_t)DMODEL*DMODEL];
__device__ bf g_WoH[(size_t)DMODEL*DMODEL], g_WoL[(size_t)DMODEL*DMODEL];
__device__ __half g_hHf[(size_t)N_TOK*DMODEL], g_hLf[(size_t)N_TOK*DMODEL];
__device__ __half g_THf[(size_t)NPAIR*DFF], g_TLf[(size_t)NPAIR*DFF];
__device__ __half g_WgF[(size_t)NEXP*DFF*DMODEL];
__device__ __half g_WuF[(size_t)NEXP*DFF*DMODEL];
__device__ __half g_WdF[(size_t)NEXP*DMODEL*DFF];
__device__ int g_cnt[NEXP], g_off[NEXP+1], g_cur[NEXP];
__device__ int g_pairtok[NPAIR], g_slotof[NPAIR], g_topidx[NPAIR];
__device__ float g_topgate[NPAIR];

__device__ __forceinline__ unsigned su32(const void* p){
    unsigned a; asm("{ .reg .u64 t; cvta.to.shared.u64 t, %1; cvt.u32.u64 %0, t; }":"=r"(a):"l"(p)); return a;
}
__device__ __forceinline__ void cp16(unsigned d, const void* s){
    asm volatile("cp.async.cg.shared.global [%0], [%1], 16;"::"r"(d),"l"(s));
}
__device__ __forceinline__ unsigned swz(unsigned off){ return off ^ ((off>>3)&0x70u); }
__device__ __forceinline__ void ldsm4(unsigned* r, unsigned a){
    asm volatile("ldmatrix.sync.aligned.m8n8.x4.shared.b16 {%0,%1,%2,%3}, [%4];"
        :"=r"(r[0]),"=r"(r[1]),"=r"(r[2]),"=r"(r[3]):"r"(a));
}
__device__ __forceinline__ void ldsm2(unsigned* r, unsigned a){
    asm volatile("ldmatrix.sync.aligned.m8n8.x2.shared.b16 {%0,%1}, [%2];"
        :"=r"(r[0]),"=r"(r[1]):"r"(a));
}
__device__ __forceinline__ void mma_bf(float* c, const unsigned* a, unsigned b0, unsigned b1){
    asm volatile("mma.sync.aligned.m16n8k16.row.col.f32.bf16.bf16.f32 "
        "{%0,%1,%2,%3},{%4,%5,%6,%7},{%8,%9},{%0,%1,%2,%3};"
        :"+f"(c[0]),"+f"(c[1]),"+f"(c[2]),"+f"(c[3])
        :"r"(a[0]),"r"(a[1]),"r"(a[2]),"r"(a[3]),"r"(b0),"r"(b1));
}
__device__ __forceinline__ void mma_hf(float* c, const unsigned* a, unsigned b0, unsigned b1){
    asm volatile("mma.sync.aligned.m16n8k16.row.col.f32.f16.f16.f32 "
        "{%0,%1,%2,%3},{%4,%5,%6,%7},{%8,%9},{%0,%1,%2,%3};"
        :"+f"(c[0]),"+f"(c[1]),"+f"(c[2]),"+f"(c[3])
        :"r"(a[0]),"r"(a[1]),"r"(a[2]),"r"(a[3]),"r"(b0),"r"(b1));
}
__device__ __forceinline__ void split2(float x, bf& h, bf& l){
    h = __float2bfloat16(x); l = __float2bfloat16(x - __bfloat162float(h));
}
__device__ __forceinline__ void split2h(float x, __half& h, __half& l){
    h = __float2half_rn(x); l = __float2half_rn(x - __half2float(h));
}

__global__ void init_counts(){ if (threadIdx.x < NEXP) g_cnt[threadIdx.x] = 0; }
__global__ void scan_offsets(){
    if (threadIdx.x == 0){ int s=0; for(int e=0;e<NEXP;e++){ g_off[e]=s; s+=g_cnt[e]; } g_off[NEXP]=s; }
    if (threadIdx.x < NEXP) g_cur[threadIdx.x] = 0;
}
__global__ void scatter_pairs(){
    int t = blockIdx.x*blockDim.x + threadIdx.x; if (t >= N_TOK) return;
    for (int k=0;k<2;k++){
        int e = g_topidx[2*t+k];
        int slot = g_off[e] + atomicAdd(&g_cur[e],1);
        g_pairtok[slot] = t; g_slotof[2*t+k] = slot;
    }
}
__global__ void convert_hilo(const float* __restrict__ x, bf* __restrict__ h, bf* __restrict__ l, int n4){
    int i = blockIdx.x*blockDim.x + threadIdx.x; if (i >= n4) return;
    float4 v = ((const float4*)x)[i];
    bf2 p0,p1,q0,q1;
    split2(v.x,p0.x,q0.x); split2(v.y,p0.y,q0.y); split2(v.z,p1.x,q1.x); split2(v.w,p1.y,q1.y);
    ((bf2*)h)[2*i]=p0; ((bf2*)h)[2*i+1]=p1; ((bf2*)l)[2*i]=q0; ((bf2*)l)[2*i+1]=q1;
}
__global__ void convert_f16(const float* __restrict__ x, __half* __restrict__ o, int n4){
    int i = blockIdx.x*blockDim.x + threadIdx.x; if (i >= n4) return;
    float4 v = ((const float4*)x)[i];
    __half2 p0, p1;
    p0.x = __float2half_rn(v.x); p0.y = __float2half_rn(v.y);
    p1.x = __float2half_rn(v.z); p1.y = __float2half_rn(v.w);
    ((__half2*)o)[2*i]=p0; ((__half2*)o)[2*i+1]=p1;
}
__global__ void rmsnorm_f16(const float* __restrict__ X, const float* __restrict__ w,
                            float* __restrict__ Y, __half* __restrict__ YH, __half* __restrict__ YL){
    int row = blockIdx.x, tid = threadIdx.x;
    float4 v = ((const float4*)(X + (ll)row*DMODEL))[tid];
    float ss = v.x*v.x+v.y*v.y+v.z*v.z+v.w*v.w;
    __shared__ float red[8];
    for (int o=16;o;o>>=1) ss += __shfl_xor_sync(~0u, ss, o);
    if ((tid&31)==0) red[tid>>5]=ss;
    __syncthreads();
    float tot = red[0]+red[1]+red[2]+red[3]+red[4]+red[5]+red[6]+red[7];
    float r = rsqrtf(tot*(1.0f/DMODEL)+EPSF);
    float4 wv = ((const float4*)w)[tid];
    float4 o4 = make_float4(v.x*r*wv.x, v.y*r*wv.y, v.z*r*wv.z, v.w*r*wv.w);
    ((float4*)(Y + (ll)row*DMODEL))[tid] = o4;
    __half2 p0,p1,q0,q1;
    split2h(o4.x,p0.x,q0.x); split2h(o4.y,p0.y,q0.y); split2h(o4.z,p1.x,q1.x); split2h(o4.w,p1.y,q1.y);
    __half2* ph=(__half2*)(YH+(ll)row*DMODEL); __half2* pl=(__half2*)(YL+(ll)row*DMODEL);
    ph[2*tid]=p0; ph[2*tid+1]=p1; pl[2*tid]=q0; pl[2*tid+1]=q1;
}
__global__ void router_kernel(const float* __restrict__ h, const float* __restrict__ Wr, const float* __restrict__ bias){
    int warp = (blockIdx.x*blockDim.x+threadIdx.x)>>5, lane = threadIdx.x&31;
    if (warp >= N_TOK) return;
    const float* hr = h + (ll)warp*DMODEL;
    float acc[NEXP];
    #pragma unroll
    for (int e=0;e<NEXP;e++) acc[e]=0.f;
    for (int d=lane; d<DMODEL; d+=32){
        float hv = hr[d];
        #pragma unroll
        for (int e=0;e<NEXP;e++) acc[e] += hv*Wr[e*DMODEL+d];
    }
    #pragma unroll
    for (int e=0;e<NEXP;e++)
        for (int o=16;o;o>>=1) acc[e] += __shfl_xor_sync(~0u, acc[e], o);
    if (lane==0){
        float b0=-1e30f,b1=-1e30f; int i0=0,i1=0;
        #pragma unroll
        for (int e=0;e<NEXP;e++){
            float v = acc[e]+bias[e];
            if (v>b0){ b1=b0;i1=i0;b0=v;i0=e; } else if (v>b1){ b1=v;i1=e; }
        }
        float m=fmaxf(acc[i0],acc[i1]);
        float e0=expf(acc[i0]-m), e1=expf(acc[i1]-m), inv=1.f/(e0+e1);
        g_topidx[2*warp]=i0; g_topidx[2*warp+1]=i1;
        g_topgate[2*warp]=e0*inv; g_topgate[2*warp+1]=e1*inv;
        atomicAdd(&g_cnt[i0],1); atomicAdd(&g_cnt[i1],1);
    }
}

// ---------- bf16 3-pass GEMM (R4-proven, non-dual path), 128x128 tile ----------
__global__ __launch_bounds__(256) void mm_bf(
    const bf* __restrict__ Ah, const bf* __restrict__ Al,
    const bf* __restrict__ B0h, const bf* __restrict__ B0l,
    float* __restrict__ C, int Mdense, int K, int Ncols)
{
    extern __shared__ char dsm[];
    int Mloc = Mdense;
    int bm = blockIdx.x*128; if (bm >= Mloc) return;
    int bn = blockIdx.y*128;
    unsigned sb = su32(dsm);
    int tid = threadIdx.x;
    int aslot = tid&7, arow0 = tid>>3;
    int ga[4];
    #pragma unroll
    for (int j=0;j<4;j++){
        int lr = bm + arow0 + 32*j; if (lr > Mloc-1) lr = Mloc-1;
        ga[j] = lr;
    }
    int w = tid>>5, lane = tid&31;
    int wm = (w>>2)*64;
    int wn = (w&3)*32;
    float acc[4][4][4];
    #pragma unroll
    for (int i=0;i<4;i++)
        #pragma unroll
        for (int j=0;j<4;j++)
            #pragma unroll
            for (int q=0;q<4;q++) acc[i][j][q] = 0.f;

    int total = K>>6;
    for (int c = -1; c < total; ++c){
        int nl = c+1;
        if (nl < total){
            unsigned base = sb + (unsigned)(nl&1)*STAGE;
            int ke = nl*64 + aslot*8;
            #pragma unroll
            for (int j=0;j<4;j++){
                unsigned sw = swz((unsigned)((arow0+32*j)*128 + aslot*16));
                cp16(base+sw,        Ah + (ll)ga[j]*K + ke);
                cp16(base+16384u+sw, Al + (ll)ga[j]*K + ke);
                int br = bn + arow0 + 32*j;
                cp16(base+32768u+sw, B0h + (ll)br*K + ke);
                cp16(base+49152u+sw, B0l + (ll)br*K + ke);
            }
            asm volatile("cp.async.commit_group;":::"memory");
        }
        if (c < 0) continue;
        if (nl < total) asm volatile("cp.async.wait_group 1;":::"memory");
        else            asm volatile("cp.async.wait_group 0;":::"memory");
        __syncthreads();

        unsigned base = sb + (unsigned)(c&1)*STAGE;
        int lrow8 = ((lane>>3)&1)*8 + (lane&7);
        #pragma unroll
        for (int ks=0; ks<4; ks++){
            int kb = ks*32 + (lane>>4)*16;
            unsigned BH[2][4], BL[2][4];
            #pragma unroll
            for (int t=0;t<2;t++){
                unsigned sw = swz((unsigned)((wn + t*16 + lrow8)*128 + kb));
                ldsm4(BH[t], base + 32768u + sw);
                ldsm4(BL[t], base + 49152u + sw);
            }
            #pragma unroll
            for (int tm=0;tm<4;tm++){
                unsigned ah[4], al[4];
                unsigned asw = swz((unsigned)((wm + tm*16 + lrow8)*128 + kb));
                ldsm4(ah, base + asw);
                ldsm4(al, base + 16384u + asw);
                #pragma unroll
                for (int t=0;t<2;t++){
                    int j0=2*t, j1=2*t+1;
                    mma_bf(acc[tm][j0], ah, BH[t][0], BH[t][2]);
                    mma_bf(acc[tm][j0], ah, BL[t][0], BL[t][2]);
                    mma_bf(acc[tm][j0], al, BH[t][0], BH[t][2]);
                    mma_bf(acc[tm][j1], ah, BH[t][1], BH[t][3]);
                    mma_bf(acc[tm][j1], ah, BL[t][1], BL[t][3]);
                    mma_bf(acc[tm][j1], al, BH[t][1], BH[t][3]);
                }
            }
        }
        __syncthreads();
    }
    #pragma unroll
    for (int tm=0;tm<4;tm++){
        int r = bm + wm + tm*16 + (lane>>2);
        #pragma unroll
        for (int j=0;j<4;j++){
            float* cc = acc[tm][j];
            int col = bn + wn + j*8 + (lane&3)*2;
            if (r < Mloc)
                *(float2*)(C + (ll)r*Ncols + col) = make_float2(cc[0],cc[1]);
            if (r+8 < Mloc)
                *(float2*)(C + (ll)(r+8)*Ncols + col) = make_float2(cc[2],cc[3]);
        }
    }
}

// ---------- fp16 2-pass grouped expert GEMM: C = (Ah+Al) * Bh^T ----------
// DUAL=1 (gateup): B = 64 gate rows + 64 up rows, epilogue silu(g)*u -> half hi/lo.
// DUAL=0 (down):   B = 128 rows of Wd, epilogue fp32 C.
// Stage: Ah 16K @0, Al 16K @16K, Bh 16K @32K = 48KB; 2 stages; 2 CTAs/SM.
template<int DUAL>
__global__ __launch_bounds__(256, 2) void mm_f16(
    const __half* __restrict__ Ah, const __half* __restrict__ Al,
    const __half* __restrict__ B0, const __half* __restrict__ B1,
    float* __restrict__ C, __half* __restrict__ TH, __half* __restrict__ TL,
    int K, int Ncols,
    const int* __restrict__ d_off, const int* __restrict__ pairtok, ll strideB)
{
    extern __shared__ char dsm[];
    int e = blockIdx.z;
    int rowBase = d_off[e], Mloc = d_off[e+1]-rowBase;
    const __half* b0 = B0 + (ll)e*strideB;
    const __half* b1 = DUAL ? (B1 + (ll)e*strideB) : nullptr;
    int bm = blockIdx.x*128; if (bm >= Mloc) return;
    int bn = blockIdx.y*(DUAL?64:128);

    unsigned sb = su32(dsm);
    int tid = threadIdx.x;
    int aslot = tid&7, arow0 = tid>>3;
    int ga[4];
    #pragma unroll
    for (int j=0;j<4;j++){
        int lr = bm + arow0 + 32*j; if (lr > Mloc-1) lr = Mloc-1;
        ga[j] = DUAL ? pairtok[rowBase+lr] : (rowBase+lr);
    }
    int w = tid>>5, lane = tid&31;
    int wm = DUAL ? (w>>1)*32 : (w>>2)*64;
    int wn = (DUAL ? (w&1) : (w&3))*32;
    constexpr int MT = DUAL ? 2 : 4;
    constexpr int NB = DUAL ? 4 : 2;

    float acc[4][4][4];   // dual: [0..1]=gate, [2..3]=up
    #pragma unroll
    for (int i=0;i<4;i++)
        #pragma unroll
        for (int j=0;j<4;j++)
            #pragma unroll
            for (int q=0;q<4;q++) acc[i][j][q] = 0.f;

    int total = K>>6;
    for (int c = -1; c < total; ++c){
        int nl = c+1;
        if (nl < total){
            unsigned base = sb + (unsigned)(nl&1)*STAGEH;
            int ke = nl*64 + aslot*8;
            #pragma unroll
            for (int j=0;j<4;j++){
                int r = arow0 + 32*j;
                unsigned sw = swz((unsigned)(r*128 + aslot*16));
                cp16(base+sw,        Ah + (ll)ga[j]*K + ke);
                cp16(base+16384u+sw, Al + (ll)ga[j]*K + ke);
                const __half* bp; int br;
                if (DUAL && r >= 64){ bp = b1; br = bn + r - 64; }
                else                { bp = b0; br = bn + r; }
                cp16(base+32768u+sw, bp + (ll)br*K + ke);
            }
            asm volatile("cp.async.commit_group;":::"memory");
        }
        if (c < 0) continue;
        if (nl < total) asm volatile("cp.async.wait_group 1;":::"memory");
        else            asm volatile("cp.async.wait_group 0;":::"memory");
        __syncthreads();

        unsigned base = sb + (unsigned)(c&1)*STAGEH;
        int lrow8 = ((lane>>3)&1)*8 + (lane&7);
        #pragma unroll
        for (int ks=0; ks<4; ks++){
            int kb = ks*32 + (lane>>4)*16;
            unsigned BH[NB][4];
            #pragma unroll
            for (int t=0;t<NB;t++){
                int nb = (DUAL && t>=2) ? (64 + wn + (t-2)*16) : (wn + t*16);
                ldsm4(BH[t], base + 32768u + swz((unsigned)((nb + lrow8)*128 + kb)));
            }
            #pragma unroll
            for (int tm=0;tm<MT;tm++){
                unsigned ah[4], al[4];
                unsigned asw = swz((unsigned)((wm + tm*16 + lrow8)*128 + kb));
                ldsm4(ah, base + asw);
                ldsm4(al, base + 16384u + asw);
                #pragma unroll
                for (int t=0;t<2;t++){
                    int j0=2*t, j1=2*t+1;
                    mma_hf(acc[tm][j0], ah, BH[t][0], BH[t][2]);
                    mma_hf(acc[tm][j0], al, BH[t][0], BH[t][2]);
                    mma_hf(acc[tm][j1], ah, BH[t][1], BH[t][3]);
                    mma_hf(acc[tm][j1], al, BH[t][1], BH[t][3]);
                    if (DUAL){
                        mma_hf(acc[2+tm][j0], ah, BH[2+t][0], BH[2+t][2]);
                        mma_hf(acc[2+tm][j0], al, BH[2+t][0], BH[2+t][2]);
                        mma_hf(acc[2+tm][j1], ah, BH[2+t][1], BH[2+t][3]);
                        mma_hf(acc[2+tm][j1], al, BH[2+t][1], BH[2+t][3]);
                    }
                }
            }
        }
        __syncthreads();
    }

    if (!DUAL){
        #pragma unroll
        for (int tm=0;tm<4;tm++){
            int r = bm + wm + tm*16 + (lane>>2);
            #pragma unroll
            for (int j=0;j<4;j++){
                float* cc = acc[tm][j];
                int col = bn + wn + j*8 + (lane&3)*2;
                if (r < Mloc)
                    *(float2*)(C + (ll)(rowBase+r)*Ncols + col) = make_float2(cc[0],cc[1]);
                if (r+8 < Mloc)
                    *(float2*)(C + (ll)(rowBase+r+8)*Ncols + col) = make_float2(cc[2],cc[3]);
            }
        }
    } else {
        #pragma unroll
        for (int tm=0;tm<2;tm++){
            int r = bm + wm + tm*16 + (lane>>2);
            #pragma unroll
            for (int j=0;j<4;j++){
                float* gg = acc[tm][j];
                float* uu = acc[2+tm][j];
                float v0 = gg[0]*uu[0]/(1.f+__expf(-gg[0]));
                float v1 = gg[1]*uu[1]/(1.f+__expf(-gg[1]));
                float v2 = gg[2]*uu[2]/(1.f+__expf(-gg[2]));
                float v3 = gg[3]*uu[3]/(1.f+__expf(-gg[3]));
                int col = bn + wn + j*8 + (lane&3)*2;
                __half2 h0,l0,h1,l1;
                split2h(v0,h0.x,l0.x); split2h(v1,h0.y,l0.y);
                split2h(v2,h1.x,l1.x); split2h(v3,h1.y,l1.y);
                if (r < Mloc){
                    *(__half2*)(TH + (ll)(rowBase+r)*Ncols + col) = h0;
                    *(__half2*)(TL + (ll)(rowBase+r)*Ncols + col) = l0;
                }
                if (r+8 < Mloc){
                    *(__half2*)(TH + (ll)(rowBase+r+8)*Ncols + col) = h1;
                    *(__half2*)(TL + (ll)(rowBase+r+8)*Ncols + col) = l1;
                }
            }
        }
    }
}

__global__ void combine_rows(const float* __restrict__ enorm, const float* __restrict__ outnorm){
    int t = blockIdx.x, tid = threadIdx.x;
    int s0=g_slotof[2*t], s1=g_slotof[2*t+1], e0=g_topidx[2*t], e1=g_topidx[2*t+1];
    float gg0=g_topgate[2*t], gg1=g_topgate[2*t+1];
    float4 a = ((const float4*)(g_Oe+(ll)s0*DMODEL))[tid];
    float4 b = ((const float4*)(g_Oe+(ll)s1*DMODEL))[tid];
    float ssa=a.x*a.x+a.y*a.y+a.z*a.z+a.w*a.w, ssb=b.x*b.x+b.y*b.y+b.z*b.z+b.w*b.w;
    __shared__ float rA[8],rB[8],rC[8];
    for (int o=16;o;o>>=1){ ssa+=__shfl_xor_sync(~0u,ssa,o); ssb+=__shfl_xor_sync(~0u,ssb,o); }
    if ((tid&31)==0){ rA[tid>>5]=ssa; rB[tid>>5]=ssb; }
    __syncthreads();
    float ta=rA[0]+rA[1]+rA[2]+rA[3]+rA[4]+rA[5]+rA[6]+rA[7];
    float tb=rB[0]+rB[1]+rB[2]+rB[3]+rB[4]+rB[5]+rB[6]+rB[7];
    float r0=rsqrtf(ta*(1.f/DMODEL)+EPSF)*gg0, r1=rsqrtf(tb*(1.f/DMODEL)+EPSF)*gg1;
    float4 w0=((const float4*)(enorm+(ll)e0*DMODEL))[tid];
    float4 w1=((const float4*)(enorm+(ll)e1*DMODEL))[tid];
    float4 c = make_float4(a.x*r0*w0.x+b.x*r1*w1.x, a.y*r0*w0.y+b.y*r1*w1.y,
                           a.z*r0*w0.z+b.z*r1*w1.z, a.w*r0*w0.w+b.w*r1*w1.w);
    float ssc=c.x*c.x+c.y*c.y+c.z*c.z+c.w*c.w;
    for (int o=16;o;o>>=1) ssc+=__shfl_xor_sync(~0u,ssc,o);
    if ((tid&31)==0) rC[tid>>5]=ssc;
    __syncthreads();
    float tc=rC[0]+rC[1]+rC[2]+rC[3]+rC[4]+rC[5]+rC[6]+rC[7];
    float rc=rsqrtf(tc*(1.f/DMODEL)+EPSF);
    float4 wo=((const float4*)outnorm)[tid];
    float4 o4=make_float4(c.x*rc*wo.x, c.y*rc*wo.y, c.z*rc*wo.z, c.w*rc*wo.w);
    bf2 p0,p1,q0,q1;
    split2(o4.x,p0.x,q0.x); split2(o4.y,p0.y,q0.y); split2(o4.z,p1.x,q1.x); split2(o4.w,p1.y,q1.y);
    bf2* ph=(bf2*)(g_yH+(ll)t*DMODEL); bf2* pl=(bf2*)(g_yL+(ll)t*DMODEL);
    ph[2*tid]=p0; ph[2*tid+1]=p1; pl[2*tid]=q0; pl[2*tid+1]=q1;
}

extern "C" void kernel_launch(void* const* d_in, const int* in_sizes, int n_in,
                              void* d_out, int out_size)
{
    const float* s          = (const float*)d_in[0];
    const float* W_in       = (const float*)d_in[1];
    const float* in_norm_w  = (const float*)d_in[2];
    const float* Wr         = (const float*)d_in[3];
    const float* expert_bias= (const float*)d_in[4];
    const float* Wg         = (const float*)d_in[5];
    const float* Wu         = (const float*)d_in[6];
    const float* Wd         = (const float*)d_in[7];
    const float* enorm_w    = (const float*)d_in[8];
    const float* out_norm_w = (const float*)d_in[9];
    const float* W_out      = (const float*)d_in[10];
    float* out = (float*)d_out;

    cudaFuncSetAttribute(mm_bf, cudaFuncAttributeMaxDynamicSharedMemorySize, SMEM_BF);
    cudaFuncSetAttribute(mm_f16<1>, cudaFuncAttributeMaxDynamicSharedMemorySize, SMEM_F16);
    cudaFuncSetAttribute(mm_f16<0>, cudaFuncAttributeMaxDynamicSharedMemorySize, SMEM_F16);

    void* p;
    #define SYM(v,T,sname) cudaGetSymbolAddress(&p,sname); T* v=(T*)p;
    SYM(h_ptr,float,g_h) SYM(Oe_ptr,float,g_Oe)
    SYM(sH,bf,g_sH) SYM(sL,bf,g_sL)
    SYM(yH,bf,g_yH) SYM(yL,bf,g_yL)
    SYM(WinH,bf,g_WinH) SYM(WinL,bf,g_WinL)
    SYM(WoH,bf,g_WoH) SYM(WoL,bf,g_WoL)
    SYM(hHf,__half,g_hHf) SYM(hLf,__half,g_hLf)
    SYM(THf,__half,g_THf) SYM(TLf,__half,g_TLf)
    SYM(WgF,__half,g_WgF) SYM(WuF,__half,g_WuF) SYM(WdF,__half,g_WdF)
    SYM(off_ptr,int,g_off) SYM(ptok,int,g_pairtok)
    #undef SYM

    init_counts<<<1,32>>>();
    int nW = DMODEL*DMODEL/4, nE = NEXP*DFF*DMODEL/4;
    convert_hilo<<<(N_TOK*DMODEL/4+255)/256,256>>>(s, sH, sL, N_TOK*DMODEL/4);
    convert_hilo<<<(nW+255)/256,256>>>(W_in, WinH, WinL, nW);
    convert_f16<<<(nE+255)/256,256>>>(Wg, WgF, nE);
    convert_f16<<<(nE+255)/256,256>>>(Wu, WuF, nE);
    convert_f16<<<(nE+255)/256,256>>>(Wd, WdF, nE);
    convert_hilo<<<(nW+255)/256,256>>>(W_out, WoH, WoL, nW);

    // h_pre = s @ W_in^T  (bf16 3-pass)
    mm_bf<<<dim3(N_TOK/128, DMODEL/128), 256, SMEM_BF>>>(
        sH, sL, WinH, WinL, h_ptr, N_TOK, DMODEL, DMODEL);
    rmsnorm_f16<<<N_TOK,256>>>(h_ptr, in_norm_w, h_ptr, hHf, hLf);
    router_kernel<<<(N_TOK*32)/256,256>>>(h_ptr, Wr, expert_bias);
    scan_offsets<<<1,32>>>();
    scatter_pairs<<<N_TOK/256,256>>>();

    // T = silu(h Wg^T) * (h Wu^T)  (fp16 2-pass, gathered, grouped, dual-B)
    mm_f16<1><<<dim3(NPAIR/128, DFF/64, NEXP), 256, SMEM_F16>>>(
        hHf, hLf, WgF, WuF, nullptr, THf, TLf,
        DMODEL, DFF, off_ptr, ptok, (ll)DFF*DMODEL);

    // Oe = T @ Wd^T  (fp16 2-pass, grouped)
    mm_f16<0><<<dim3(NPAIR/128, DMODEL/128, NEXP), 256, SMEM_F16>>>(
        THf, TLf, WdF, nullptr, Oe_ptr, nullptr, nullptr,
        DFF, DMODEL, off_ptr, nullptr, (ll)DMODEL*DFF);

    combine_rows<<<N_TOK,256>>>(enorm_w, out_norm_w);

    // out = y @ W_out^T  (bf16 3-pass)
    mm_bf<<<dim3(N_TOK/128, DMODEL/128), 256, SMEM_BF>>>(
        yH, yL, WoH, WoL, out, N_TOK, DMODEL, DMODEL);
}

// round 9
// speedup vs baseline: 1.1716x; 1.1713x over previous
#include <cuda_runtime.h>
#include <cuda_bf16.h>
#include <cuda_fp16.h>

#define N_TOK 8192
#define DMODEL 1024
#define DFF 4096
#define NEXP 8
#define NPAIR (N_TOK * 2)
#define EPSF 1.1920928955078125e-07f
#define STAGE 65536u
#define SMEM_BF (2 * 65536)
typedef __nv_bfloat16 bf;
typedef __nv_bfloat162 bf2;
typedef long long ll;

__device__ float g_h[(size_t)N_TOK * DMODEL];
__device__ float g_Oe[(size_t)NPAIR * DMODEL];
__device__ bf g_sH[(size_t)N_TOK*DMODEL], g_sL[(size_t)N_TOK*DMODEL];
__device__ bf g_WinH[(size_t)DMODEL*DMODEL], g_WinL[(size_t)DMODEL*DMODEL];
__device__ __half g_hHf[(size_t)N_TOK*DMODEL], g_hLf[(size_t)N_TOK*DMODEL];
__device__ __half g_yHf[(size_t)N_TOK*DMODEL], g_yLf[(size_t)N_TOK*DMODEL];
__device__ __half g_THf[(size_t)NPAIR*DFF];
__device__ __half g_WgF[(size_t)NEXP*DFF*DMODEL];
__device__ __half g_WuF[(size_t)NEXP*DFF*DMODEL];
__device__ __half g_WdF[(size_t)NEXP*DMODEL*DFF];
__device__ __half g_WoF[(size_t)DMODEL*DMODEL];
__device__ int g_cnt[NEXP], g_off[NEXP+1], g_cur[NEXP];
__device__ int g_pairtok[NPAIR], g_slotof[NPAIR], g_topidx[NPAIR];
__device__ float g_topgate[NPAIR];

__device__ __forceinline__ unsigned su32(const void* p){
    unsigned a; asm("{ .reg .u64 t; cvta.to.shared.u64 t, %1; cvt.u32.u64 %0, t; }":"=r"(a):"l"(p)); return a;
}
__device__ __forceinline__ void cp16(unsigned d, const void* s){
    asm volatile("cp.async.cg.shared.global [%0], [%1], 16;"::"r"(d),"l"(s));
}
__device__ __forceinline__ unsigned swz(unsigned off){ return off ^ ((off>>3)&0x70u); }
__device__ __forceinline__ void ldsm4(unsigned* r, unsigned a){
    asm volatile("ldmatrix.sync.aligned.m8n8.x4.shared.b16 {%0,%1,%2,%3}, [%4];"
        :"=r"(r[0]),"=r"(r[1]),"=r"(r[2]),"=r"(r[3]):"r"(a));
}
__device__ __forceinline__ void mma_bf(float* c, const unsigned* a, unsigned b0, unsigned b1){
    asm volatile("mma.sync.aligned.m16n8k16.row.col.f32.bf16.bf16.f32 "
        "{%0,%1,%2,%3},{%4,%5,%6,%7},{%8,%9},{%0,%1,%2,%3};"
        :"+f"(c[0]),"+f"(c[1]),"+f"(c[2]),"+f"(c[3])
        :"r"(a[0]),"r"(a[1]),"r"(a[2]),"r"(a[3]),"r"(b0),"r"(b1));
}
__device__ __forceinline__ void mma_hf(float* c, const unsigned* a, unsigned b0, unsigned b1){
    asm volatile("mma.sync.aligned.m16n8k16.row.col.f32.f16.f16.f32 "
        "{%0,%1,%2,%3},{%4,%5,%6,%7},{%8,%9},{%0,%1,%2,%3};"
        :"+f"(c[0]),"+f"(c[1]),"+f"(c[2]),"+f"(c[3])
        :"r"(a[0]),"r"(a[1]),"r"(a[2]),"r"(a[3]),"r"(b0),"r"(b1));
}
__device__ __forceinline__ void split2(float x, bf& h, bf& l){
    h = __float2bfloat16(x); l = __float2bfloat16(x - __bfloat162float(h));
}
__device__ __forceinline__ void split2h(float x, __half& h, __half& l){
    h = __float2half_rn(x); l = __float2half_rn(x - __half2float(h));
}

__global__ void init_counts(){ if (threadIdx.x < NEXP) g_cnt[threadIdx.x] = 0; }
__global__ void scan_offsets(){
    if (threadIdx.x == 0){ int s=0; for(int e=0;e<NEXP;e++){ g_off[e]=s; s+=g_cnt[e]; } g_off[NEXP]=s; }
    if (threadIdx.x < NEXP) g_cur[threadIdx.x] = 0;
}
__global__ void scatter_pairs(){
    int t = blockIdx.x*blockDim.x + threadIdx.x; if (t >= N_TOK) return;
    for (int k=0;k<2;k++){
        int e = g_topidx[2*t+k];
        int slot = g_off[e] + atomicAdd(&g_cur[e],1);
        g_pairtok[slot] = t; g_slotof[2*t+k] = slot;
    }
}
__global__ void convert_hilo(const float* __restrict__ x, bf* __restrict__ h, bf* __restrict__ l, int n4){
    int i = blockIdx.x*blockDim.x + threadIdx.x; if (i >= n4) return;
    float4 v = ((const float4*)x)[i];
    bf2 p0,p1,q0,q1;
    split2(v.x,p0.x,q0.x); split2(v.y,p0.y,q0.y); split2(v.z,p1.x,q1.x); split2(v.w,p1.y,q1.y);
    ((bf2*)h)[2*i]=p0; ((bf2*)h)[2*i+1]=p1; ((bf2*)l)[2*i]=q0; ((bf2*)l)[2*i+1]=q1;
}
__global__ void convert_f16(const float* __restrict__ x, __half* __restrict__ o, int n4){
    int i = blockIdx.x*blockDim.x + threadIdx.x; if (i >= n4) return;
    float4 v = ((const float4*)x)[i];
    __half2 p0, p1;
    p0.x = __float2half_rn(v.x); p0.y = __float2half_rn(v.y);
    p1.x = __float2half_rn(v.z); p1.y = __float2half_rn(v.w);
    ((__half2*)o)[2*i]=p0; ((__half2*)o)[2*i+1]=p1;
}
__global__ void rmsnorm_f16(const float* __restrict__ X, const float* __restrict__ w,
                            float* __restrict__ Y, __half* __restrict__ YH, __half* __restrict__ YL){
    int row = blockIdx.x, tid = threadIdx.x;
    float4 v = ((const float4*)(X + (ll)row*DMODEL))[tid];
    float ss = v.x*v.x+v.y*v.y+v.z*v.z+v.w*v.w;
    __shared__ float red[8];
    for (int o=16;o;o>>=1) ss += __shfl_xor_sync(~0u, ss, o);
    if ((tid&31)==0) red[tid>>5]=ss;
    __syncthreads();
    float tot = red[0]+red[1]+red[2]+red[3]+red[4]+red[5]+red[6]+red[7];
    float r = rsqrtf(tot*(1.0f/DMODEL)+EPSF);
    float4 wv = ((const float4*)w)[tid];
    float4 o4 = make_float4(v.x*r*wv.x, v.y*r*wv.y, v.z*r*wv.z, v.w*r*wv.w);
    ((float4*)(Y + (ll)row*DMODEL))[tid] = o4;
    __half2 p0,p1,q0,q1;
    split2h(o4.x,p0.x,q0.x); split2h(o4.y,p0.y,q0.y); split2h(o4.z,p1.x,q1.x); split2h(o4.w,p1.y,q1.y);
    __half2* ph=(__half2*)(YH+(ll)row*DMODEL); __half2* pl=(__half2*)(YL+(ll)row*DMODEL);
    ph[2*tid]=p0; ph[2*tid+1]=p1; pl[2*tid]=q0; pl[2*tid+1]=q1;
}
__global__ void router_kernel(const float* __restrict__ h, const float* __restrict__ Wr, const float* __restrict__ bias){
    int warp = (blockIdx.x*blockDim.x+threadIdx.x)>>5, lane = threadIdx.x&31;
    if (warp >= N_TOK) return;
    const float* hr = h + (ll)warp*DMODEL;
    float acc[NEXP];
    #pragma unroll
    for (int e=0;e<NEXP;e++) acc[e]=0.f;
    for (int d=lane; d<DMODEL; d+=32){
        float hv = hr[d];
        #pragma unroll
        for (int e=0;e<NEXP;e++) acc[e] += hv*Wr[e*DMODEL+d];
    }
    #pragma unroll
    for (int e=0;e<NEXP;e++)
        for (int o=16;o;o>>=1) acc[e] += __shfl_xor_sync(~0u, acc[e], o);
    if (lane==0){
        float b0=-1e30f,b1=-1e30f; int i0=0,i1=0;
        #pragma unroll
        for (int e=0;e<NEXP;e++){
            float v = acc[e]+bias[e];
            if (v>b0){ b1=b0;i1=i0;b0=v;i0=e; } else if (v>b1){ b1=v;i1=e; }
        }
        float m=fmaxf(acc[i0],acc[i1]);
        float e0=expf(acc[i0]-m), e1=expf(acc[i1]-m), inv=1.f/(e0+e1);
        g_topidx[2*warp]=i0; g_topidx[2*warp+1]=i1;
        g_topgate[2*warp]=e0*inv; g_topgate[2*warp+1]=e1*inv;
        atomicAdd(&g_cnt[i0],1); atomicAdd(&g_cnt[i1],1);
    }
}

// ---------- bf16 3-pass dense GEMM (in-proj; protects router precision) ----------
__global__ __launch_bounds__(256) void mm_bf(
    const bf* __restrict__ Ah, const bf* __restrict__ Al,
    const bf* __restrict__ B0h, const bf* __restrict__ B0l,
    float* __restrict__ C, int Mdense, int K, int Ncols)
{
    extern __shared__ char dsm[];
    int Mloc = Mdense;
    int bm = blockIdx.x*128; if (bm >= Mloc) return;
    int bn = blockIdx.y*128;
    unsigned sb = su32(dsm);
    int tid = threadIdx.x;
    int aslot = tid&7, arow0 = tid>>3;
    int w = tid>>5, lane = tid&31;
    int wm = (w>>2)*64, wn = (w&3)*32;
    float acc[4][4][4];
    #pragma unroll
    for (int i=0;i<4;i++)
        #pragma unroll
        for (int j=0;j<4;j++)
            #pragma unroll
            for (int q=0;q<4;q++) acc[i][j][q] = 0.f;

    int total = K>>6;
    for (int c = -1; c < total; ++c){
        int nl = c+1;
        if (nl < total){
            unsigned base = sb + (unsigned)(nl&1)*STAGE;
            int ke = nl*64 + aslot*8;
            #pragma unroll
            for (int j=0;j<4;j++){
                int r = arow0 + 32*j;
                unsigned sw = swz((unsigned)(r*128 + aslot*16));
                int ar = bm + r;
                cp16(base+sw,        Ah + (ll)ar*K + ke);
                cp16(base+16384u+sw, Al + (ll)ar*K + ke);
                int br = bn + r;
                cp16(base+32768u+sw, B0h + (ll)br*K + ke);
                cp16(base+49152u+sw, B0l + (ll)br*K + ke);
            }
            asm volatile("cp.async.commit_group;":::"memory");
        }
        if (c < 0) continue;
        if (nl < total) asm volatile("cp.async.wait_group 1;":::"memory");
        else            asm volatile("cp.async.wait_group 0;":::"memory");
        __syncthreads();

        unsigned base = sb + (unsigned)(c&1)*STAGE;
        int lrow8 = ((lane>>3)&1)*8 + (lane&7);
        #pragma unroll
        for (int ks=0; ks<4; ks++){
            int kb = ks*32 + (lane>>4)*16;
            unsigned BH[2][4], BL[2][4];
            #pragma unroll
            for (int t=0;t<2;t++){
                unsigned sw = swz((unsigned)((wn + t*16 + lrow8)*128 + kb));
                ldsm4(BH[t], base + 32768u + sw);
                ldsm4(BL[t], base + 49152u + sw);
            }
            #pragma unroll
            for (int tm=0;tm<4;tm++){
                unsigned ah[4], al[4];
                unsigned asw = swz((unsigned)((wm + tm*16 + lrow8)*128 + kb));
                ldsm4(ah, base + asw);
                ldsm4(al, base + 16384u + asw);
                #pragma unroll
                for (int t=0;t<2;t++){
                    int j0=2*t, j1=2*t+1;
                    mma_bf(acc[tm][j0], ah, BH[t][0], BH[t][2]);
                    mma_bf(acc[tm][j0], ah, BL[t][0], BL[t][2]);
                    mma_bf(acc[tm][j0], al, BH[t][0], BH[t][2]);
                    mma_bf(acc[tm][j1], ah, BH[t][1], BH[t][3]);
                    mma_bf(acc[tm][j1], ah, BL[t][1], BL[t][3]);
                    mma_bf(acc[tm][j1], al, BH[t][1], BH[t][3]);
                }
            }
        }
        __syncthreads();
    }
    #pragma unroll
    for (int tm=0;tm<4;tm++){
        int r = bm + wm + tm*16 + (lane>>2);
        #pragma unroll
        for (int j=0;j<4;j++){
            float* cc = acc[tm][j];
            int col = bn + wn + j*8 + (lane&3)*2;
            *(float2*)(C + (ll)r*Ncols + col) = make_float2(cc[0],cc[1]);
            *(float2*)(C + (ll)(r+8)*Ncols + col) = make_float2(cc[2],cc[3]);
        }
    }
}

// ---------- fp16 GEMM, templated: ALO = A has lo plane (2-pass), DUAL = gate+up fused ----------
// DUAL=1: B = 64 gate + 64 up rows, epilogue silu(g)*u -> single fp16 TH.
// Stage bytes: A (16K or 32K) + B 16K. 2 stages, 2 CTAs/SM.
template<int DUAL, int ALO, int GROUPED>
__global__ __launch_bounds__(256, 2) void mm_f16(
    const __half* __restrict__ Ah, const __half* __restrict__ Al,
    const __half* __restrict__ B0, const __half* __restrict__ B1,
    float* __restrict__ C, __half* __restrict__ TH,
    int Mdense, int K, int Ncols,
    const int* __restrict__ d_off, const int* __restrict__ pairtok, ll strideB)
{
    extern __shared__ char dsm[];
    constexpr unsigned ASZ = ALO ? 32768u : 16384u;
    constexpr unsigned STG = ASZ + 16384u;
    int rowBase = 0, Mloc = Mdense;
    const __half *b0 = B0, *b1 = B1;
    if (GROUPED){
        int e = blockIdx.z;
        rowBase = d_off[e]; Mloc = d_off[e+1]-rowBase;
        b0 += (ll)e*strideB;
        if (DUAL) b1 += (ll)e*strideB;
    }
    int bm = blockIdx.x*128; if (bm >= Mloc) return;
    int bn = blockIdx.y*(DUAL?64:128);

    unsigned sb = su32(dsm);
    int tid = threadIdx.x;
    int aslot = tid&7, arow0 = tid>>3;
    int ga[4];
    #pragma unroll
    for (int j=0;j<4;j++){
        int lr = bm + arow0 + 32*j; if (lr > Mloc-1) lr = Mloc-1;
        ga[j] = (GROUPED && DUAL) ? pairtok[rowBase+lr] : (rowBase+lr);
    }
    int w = tid>>5, lane = tid&31;
    int wm = DUAL ? (w>>1)*32 : (w>>2)*64;
    int wn = (DUAL ? (w&1) : (w&3))*32;
    constexpr int MT = DUAL ? 2 : 4;
    constexpr int NB = DUAL ? 4 : 2;

    float acc[4][4][4];   // dual: [0..1]=gate, [2..3]=up
    #pragma unroll
    for (int i=0;i<4;i++)
        #pragma unroll
        for (int j=0;j<4;j++)
            #pragma unroll
            for (int q=0;q<4;q++) acc[i][j][q] = 0.f;

    int total = K>>6;
    for (int c = -1; c < total; ++c){
        int nl = c+1;
        if (nl < total){
            unsigned base = sb + (unsigned)(nl&1)*STG;
            int ke = nl*64 + aslot*8;
            #pragma unroll
            for (int j=0;j<4;j++){
                int r = arow0 + 32*j;
                unsigned sw = swz((unsigned)(r*128 + aslot*16));
                cp16(base+sw, Ah + (ll)ga[j]*K + ke);
                if (ALO) cp16(base+16384u+sw, Al + (ll)ga[j]*K + ke);
                const __half* bp; int br;
                if (DUAL && r >= 64){ bp = b1; br = bn + r - 64; }
                else                { bp = b0; br = bn + r; }
                cp16(base+ASZ+sw, bp + (ll)br*K + ke);
            }
            asm volatile("cp.async.commit_group;":::"memory");
        }
        if (c < 0) continue;
        if (nl < total) asm volatile("cp.async.wait_group 1;":::"memory");
        else            asm volatile("cp.async.wait_group 0;":::"memory");
        __syncthreads();

        unsigned base = sb + (unsigned)(c&1)*STG;
        int lrow8 = ((lane>>3)&1)*8 + (lane&7);
        #pragma unroll
        for (int ks=0; ks<4; ks++){
            int kb = ks*32 + (lane>>4)*16;
            unsigned BH[NB][4];
            #pragma unroll
            for (int t=0;t<NB;t++){
                int nb = (DUAL && t>=2) ? (64 + wn + (t-2)*16) : (wn + t*16);
                ldsm4(BH[t], base + ASZ + swz((unsigned)((nb + lrow8)*128 + kb)));
            }
            #pragma unroll
            for (int tm=0;tm<MT;tm++){
                unsigned ah[4], al[4];
                unsigned asw = swz((unsigned)((wm + tm*16 + lrow8)*128 + kb));
                ldsm4(ah, base + asw);
                if (ALO) ldsm4(al, base + 16384u + asw);
                #pragma unroll
                for (int t=0;t<2;t++){
                    int j0=2*t, j1=2*t+1;
                    mma_hf(acc[tm][j0], ah, BH[t][0], BH[t][2]);
                    mma_hf(acc[tm][j1], ah, BH[t][1], BH[t][3]);
                    if (ALO){
                        mma_hf(acc[tm][j0], al, BH[t][0], BH[t][2]);
                        mma_hf(acc[tm][j1], al, BH[t][1], BH[t][3]);
                    }
                    if (DUAL){
                        mma_hf(acc[2+tm][j0], ah, BH[2+t][0], BH[2+t][2]);
                        mma_hf(acc[2+tm][j1], ah, BH[2+t][1], BH[2+t][3]);
                        if (ALO){
                            mma_hf(acc[2+tm][j0], al, BH[2+t][0], BH[2+t][2]);
                            mma_hf(acc[2+tm][j1], al, BH[2+t][1], BH[2+t][3]);
                        }
                    }
                }
            }
        }
        __syncthreads();
    }

    if (!DUAL){
        #pragma unroll
        for (int tm=0;tm<4;tm++){
            int r = bm + wm + tm*16 + (lane>>2);
            #pragma unroll
            for (int j=0;j<4;j++){
                float* cc = acc[tm][j];
                int col = bn + wn + j*8 + (lane&3)*2;
                if (r < Mloc)
                    *(float2*)(C + (ll)(rowBase+r)*Ncols + col) = make_float2(cc[0],cc[1]);
                if (r+8 < Mloc)
                    *(float2*)(C + (ll)(rowBase+r+8)*Ncols + col) = make_float2(cc[2],cc[3]);
            }
        }
    } else {
        #pragma unroll
        for (int tm=0;tm<2;tm++){
            int r = bm + wm + tm*16 + (lane>>2);
            #pragma unroll
            for (int j=0;j<4;j++){
                float* gg = acc[tm][j];
                float* uu = acc[2+tm][j];
                float v0 = gg[0]*uu[0]/(1.f+__expf(-gg[0]));
                float v1 = gg[1]*uu[1]/(1.f+__expf(-gg[1]));
                float v2 = gg[2]*uu[2]/(1.f+__expf(-gg[2]));
                float v3 = gg[3]*uu[3]/(1.f+__expf(-gg[3]));
                int col = bn + wn + j*8 + (lane&3)*2;
                __half2 h0, h1;
                h0.x = __float2half_rn(v0); h0.y = __float2half_rn(v1);
                h1.x = __float2half_rn(v2); h1.y = __float2half_rn(v3);
                if (r < Mloc)
                    *(__half2*)(TH + (ll)(rowBase+r)*Ncols + col) = h0;
                if (r+8 < Mloc)
                    *(__half2*)(TH + (ll)(rowBase+r+8)*Ncols + col) = h1;
            }
        }
    }
}

__global__ void combine_rows(const float* __restrict__ enorm, const float* __restrict__ outnorm){
    int t = blockIdx.x, tid = threadIdx.x;
    int s0=g_slotof[2*t], s1=g_slotof[2*t+1], e0=g_topidx[2*t], e1=g_topidx[2*t+1];
    float gg0=g_topgate[2*t], gg1=g_topgate[2*t+1];
    float4 a = ((const float4*)(g_Oe+(ll)s0*DMODEL))[tid];
    float4 b = ((const float4*)(g_Oe+(ll)s1*DMODEL))[tid];
    float ssa=a.x*a.x+a.y*a.y+a.z*a.z+a.w*a.w, ssb=b.x*b.x+b.y*b.y+b.z*b.z+b.w*b.w;
    __shared__ float rA[8],rB[8],rC[8];
    for (int o=16;o;o>>=1){ ssa+=__shfl_xor_sync(~0u,ssa,o); ssb+=__shfl_xor_sync(~0u,ssb,o); }
    if ((tid&31)==0){ rA[tid>>5]=ssa; rB[tid>>5]=ssb; }
    __syncthreads();
    float ta=rA[0]+rA[1]+rA[2]+rA[3]+rA[4]+rA[5]+rA[6]+rA[7];
    float tb=rB[0]+rB[1]+rB[2]+rB[3]+rB[4]+rB[5]+rB[6]+rB[7];
    float r0=rsqrtf(ta*(1.f/DMODEL)+EPSF)*gg0, r1=rsqrtf(tb*(1.f/DMODEL)+EPSF)*gg1;
    float4 w0=((const float4*)(enorm+(ll)e0*DMODEL))[tid];
    float4 w1=((const float4*)(enorm+(ll)e1*DMODEL))[tid];
    float4 c = make_float4(a.x*r0*w0.x+b.x*r1*w1.x, a.y*r0*w0.y+b.y*r1*w1.y,
                           a.z*r0*w0.z+b.z*r1*w1.z, a.w*r0*w0.w+b.w*r1*w1.w);
    float ssc=c.x*c.x+c.y*c.y+c.z*c.z+c.w*c.w;
    for (int o=16;o;o>>=1) ssc+=__shfl_xor_sync(~0u,ssc,o);
    if ((tid&31)==0) rC[tid>>5]=ssc;
    __syncthreads();
    float tc=rC[0]+rC[1]+rC[2]+rC[3]+rC[4]+rC[5]+rC[6]+rC[7];
    float rc=rsqrtf(tc*(1.f/DMODEL)+EPSF);
    float4 wo=((const float4*)outnorm)[tid];
    float4 o4=make_float4(c.x*rc*wo.x, c.y*rc*wo.y, c.z*rc*wo.z, c.w*rc*wo.w);
    __half2 p0,p1,q0,q1;
    split2h(o4.x,p0.x,q0.x); split2h(o4.y,p0.y,q0.y); split2h(o4.z,p1.x,q1.x); split2h(o4.w,p1.y,q1.y);
    __half2* ph=(__half2*)(g_yHf+(ll)t*DMODEL); __half2* pl=(__half2*)(g_yLf+(ll)t*DMODEL);
    ph[2*tid]=p0; ph[2*tid+1]=p1; pl[2*tid]=q0; pl[2*tid+1]=q1;
}

extern "C" void kernel_launch(void* const* d_in, const int* in_sizes, int n_in,
                              void* d_out, int out_size)
{
    const float* s          = (const float*)d_in[0];
    const float* W_in       = (const float*)d_in[1];
    const float* in_norm_w  = (const float*)d_in[2];
    const float* Wr         = (const float*)d_in[3];
    const float* expert_bias= (const float*)d_in[4];
    const float* Wg         = (const float*)d_in[5];
    const float* Wu         = (const float*)d_in[6];
    const float* Wd         = (const float*)d_in[7];
    const float* enorm_w    = (const float*)d_in[8];
    const float* out_norm_w = (const float*)d_in[9];
    const float* W_out      = (const float*)d_in[10];
    float* out = (float*)d_out;

    cudaFuncSetAttribute(mm_bf, cudaFuncAttributeMaxDynamicSharedMemorySize, SMEM_BF);
    cudaFuncSetAttribute(mm_f16<1,1,1>, cudaFuncAttributeMaxDynamicSharedMemorySize, 2*49152);
    cudaFuncSetAttribute(mm_f16<0,0,1>, cudaFuncAttributeMaxDynamicSharedMemorySize, 2*32768);
    cudaFuncSetAttribute(mm_f16<0,1,0>, cudaFuncAttributeMaxDynamicSharedMemorySize, 2*49152);

    void* p;
    #define SYM(v,T,sname) cudaGetSymbolAddress(&p,sname); T* v=(T*)p;
    SYM(h_ptr,float,g_h) SYM(Oe_ptr,float,g_Oe)
    SYM(sH,bf,g_sH) SYM(sL,bf,g_sL)
    SYM(WinH,bf,g_WinH) SYM(WinL,bf,g_WinL)
    SYM(hHf,__half,g_hHf) SYM(hLf,__half,g_hLf)
    SYM(yHf,__half,g_yHf) SYM(yLf,__half,g_yLf)
    SYM(THf,__half,g_THf)
    SYM(WgF,__half,g_WgF) SYM(WuF,__half,g_WuF) SYM(WdF,__half,g_WdF) SYM(WoF,__half,g_WoF)
    SYM(off_ptr,int,g_off) SYM(ptok,int,g_pairtok)
    #undef SYM

    init_counts<<<1,32>>>();
    int nW = DMODEL*DMODEL/4, nE = NEXP*DFF*DMODEL/4;
    convert_hilo<<<(N_TOK*DMODEL/4+255)/256,256>>>(s, sH, sL, N_TOK*DMODEL/4);
    convert_hilo<<<(nW+255)/256,256>>>(W_in, WinH, WinL, nW);
    convert_f16<<<(nE+255)/256,256>>>(Wg, WgF, nE);
    convert_f16<<<(nE+255)/256,256>>>(Wu, WuF, nE);
    convert_f16<<<(nE+255)/256,256>>>(Wd, WdF, nE);
    convert_f16<<<(nW+255)/256,256>>>(W_out, WoF, nW);

    // h_pre = s @ W_in^T  (bf16 3-pass; protects router)
    mm_bf<<<dim3(N_TOK/128, DMODEL/128), 256, SMEM_BF>>>(
        sH, sL, WinH, WinL, h_ptr, N_TOK, DMODEL, DMODEL);
    rmsnorm_f16<<<N_TOK,256>>>(h_ptr, in_norm_w, h_ptr, hHf, hLf);
    router_kernel<<<(N_TOK*32)/256,256>>>(h_ptr, Wr, expert_bias);
    scan_offsets<<<1,32>>>();
    scatter_pairs<<<N_TOK/256,256>>>();

    // T = silu(h Wg^T) * (h Wu^T)  (fp16 2-pass A, single-fp16 T out)
    mm_f16<1,1,1><<<dim3(NPAIR/128, DFF/64, NEXP), 256, 2*49152>>>(
        hHf, hLf, WgF, WuF, nullptr, THf,
        0, DMODEL, DFF, off_ptr, ptok, (ll)DFF*DMODEL);

    // Oe = T @ Wd^T  (fp16 1-pass, grouped)
    mm_f16<0,0,1><<<dim3(NPAIR/128, DMODEL/128, NEXP), 256, 2*32768>>>(
        THf, nullptr, WdF, nullptr, Oe_ptr, nullptr,
        0, DFF, DMODEL, off_ptr, nullptr, (ll)DMODEL*DFF);

    combine_rows<<<N_TOK,256>>>(enorm_w, out_norm_w);

    // out = y @ W_out^T  (fp16 2-pass, dense)
    mm_f16<0,1,0><<<dim3(N_TOK/128, DMODEL/128, 1), 256, 2*49152>>>(
        yHf, yLf, WoF, nullptr, out, nullptr,
        N_TOK, DMODEL, DMODEL, nullptr, nullptr, 0);
}

// round 10
// speedup vs baseline: 1.6429x; 1.4022x over previous
#include <cuda_runtime.h>
#include <cuda_bf16.h>
#include <cuda_fp16.h>

#define N_TOK 8192
#define DMODEL 1024
#define DFF 4096
#define NEXP 8
#define NPAIR (N_TOK * 2)
#define EPSF 1.1920928955078125e-07f
#define STAGE 65536u
#define SMEM_BF (2 * 65536)
typedef __nv_bfloat16 bf;
typedef __nv_bfloat162 bf2;
typedef long long ll;

__device__ float g_h[(size_t)N_TOK * DMODEL];
__device__ float g_Oe[(size_t)NPAIR * DMODEL];
__device__ bf g_sH[(size_t)N_TOK*DMODEL], g_sL[(size_t)N_TOK*DMODEL];
__device__ bf g_WinH[(size_t)DMODEL*DMODEL], g_WinL[(size_t)DMODEL*DMODEL];
__device__ __half g_hHf[(size_t)N_TOK*DMODEL];
__device__ __half g_yHf[(size_t)N_TOK*DMODEL], g_yLf[(size_t)N_TOK*DMODEL];
__device__ __half g_THf[(size_t)NPAIR*DFF];
__device__ __half g_WgF[(size_t)NEXP*DFF*DMODEL];
__device__ __half g_WuF[(size_t)NEXP*DFF*DMODEL];
__device__ __half g_WdF[(size_t)NEXP*DMODEL*DFF];
__device__ __half g_WoF[(size_t)DMODEL*DMODEL];
__device__ int g_cnt[NEXP], g_off[NEXP+1], g_cur[NEXP];
__device__ int g_pairtok[NPAIR], g_slotof[NPAIR], g_topidx[NPAIR];
__device__ float g_topgate[NPAIR];

__device__ __forceinline__ unsigned su32(const void* p){
    unsigned a; asm("{ .reg .u64 t; cvta.to.shared.u64 t, %1; cvt.u32.u64 %0, t; }":"=r"(a):"l"(p)); return a;
}
__device__ __forceinline__ void cp16(unsigned d, const void* s){
    asm volatile("cp.async.cg.shared.global [%0], [%1], 16;"::"r"(d),"l"(s));
}
__device__ __forceinline__ unsigned swz(unsigned off){ return off ^ ((off>>3)&0x70u); }
__device__ __forceinline__ void ldsm4(unsigned* r, unsigned a){
    asm volatile("ldmatrix.sync.aligned.m8n8.x4.shared.b16 {%0,%1,%2,%3}, [%4];"
        :"=r"(r[0]),"=r"(r[1]),"=r"(r[2]),"=r"(r[3]):"r"(a));
}
__device__ __forceinline__ void mma_bf(float* c, const unsigned* a, unsigned b0, unsigned b1){
    asm volatile("mma.sync.aligned.m16n8k16.row.col.f32.bf16.bf16.f32 "
        "{%0,%1,%2,%3},{%4,%5,%6,%7},{%8,%9},{%0,%1,%2,%3};"
        :"+f"(c[0]),"+f"(c[1]),"+f"(c[2]),"+f"(c[3])
        :"r"(a[0]),"r"(a[1]),"r"(a[2]),"r"(a[3]),"r"(b0),"r"(b1));
}
__device__ __forceinline__ void mma_hf(float* c, const unsigned* a, unsigned b0, unsigned b1){
    asm volatile("mma.sync.aligned.m16n8k16.row.col.f32.f16.f16.f32 "
        "{%0,%1,%2,%3},{%4,%5,%6,%7},{%8,%9},{%0,%1,%2,%3};"
        :"+f"(c[0]),"+f"(c[1]),"+f"(c[2]),"+f"(c[3])
        :"r"(a[0]),"r"(a[1]),"r"(a[2]),"r"(a[3]),"r"(b0),"r"(b1));
}
__device__ __forceinline__ void split2(float x, bf& h, bf& l){
    h = __float2bfloat16(x); l = __float2bfloat16(x - __bfloat162float(h));
}
__device__ __forceinline__ void split2h(float x, __half& h, __half& l){
    h = __float2half_rn(x); l = __float2half_rn(x - __half2float(h));
}

__global__ void init_counts(){ if (threadIdx.x < NEXP) g_cnt[threadIdx.x] = 0; }
__global__ void scan_offsets(){
    if (threadIdx.x == 0){ int s=0; for(int e=0;e<NEXP;e++){ g_off[e]=s; s+=g_cnt[e]; } g_off[NEXP]=s; }
    if (threadIdx.x < NEXP) g_cur[threadIdx.x] = 0;
}
__global__ void scatter_pairs(){
    int t = blockIdx.x*blockDim.x + threadIdx.x; if (t >= N_TOK) return;
    for (int k=0;k<2;k++){
        int e = g_topidx[2*t+k];
        int slot = g_off[e] + atomicAdd(&g_cur[e],1);
        g_pairtok[slot] = t; g_slotof[2*t+k] = slot;
    }
}
__global__ void convert_hilo(const float* __restrict__ x, bf* __restrict__ h, bf* __restrict__ l, int n4){
    int i = blockIdx.x*blockDim.x + threadIdx.x; if (i >= n4) return;
    float4 v = ((const float4*)x)[i];
    bf2 p0,p1,q0,q1;
    split2(v.x,p0.x,q0.x); split2(v.y,p0.y,q0.y); split2(v.z,p1.x,q1.x); split2(v.w,p1.y,q1.y);
    ((bf2*)h)[2*i]=p0; ((bf2*)h)[2*i+1]=p1; ((bf2*)l)[2*i]=q0; ((bf2*)l)[2*i+1]=q1;
}
__global__ void convert_f16(const float* __restrict__ x, __half* __restrict__ o, int n4){
    int i = blockIdx.x*blockDim.x + threadIdx.x; if (i >= n4) return;
    float4 v = ((const float4*)x)[i];
    __half2 p0, p1;
    p0.x = __float2half_rn(v.x); p0.y = __float2half_rn(v.y);
    p1.x = __float2half_rn(v.z); p1.y = __float2half_rn(v.w);
    ((__half2*)o)[2*i]=p0; ((__half2*)o)[2*i+1]=p1;
}
__global__ void rmsnorm_f16(const float* __restrict__ X, const float* __restrict__ w,
                            float* __restrict__ Y, __half* __restrict__ YH){
    int row = blockIdx.x, tid = threadIdx.x;
    float4 v = ((const float4*)(X + (ll)row*DMODEL))[tid];
    float ss = v.x*v.x+v.y*v.y+v.z*v.z+v.w*v.w;
    __shared__ float red[8];
    for (int o=16;o;o>>=1) ss += __shfl_xor_sync(~0u, ss, o);
    if ((tid&31)==0) red[tid>>5]=ss;
    __syncthreads();
    float tot = red[0]+red[1]+red[2]+red[3]+red[4]+red[5]+red[6]+red[7];
    float r = rsqrtf(tot*(1.0f/DMODEL)+EPSF);
    float4 wv = ((const float4*)w)[tid];
    float4 o4 = make_float4(v.x*r*wv.x, v.y*r*wv.y, v.z*r*wv.z, v.w*r*wv.w);
    ((float4*)(Y + (ll)row*DMODEL))[tid] = o4;
    __half2 p0,p1;
    p0.x = __float2half_rn(o4.x); p0.y = __float2half_rn(o4.y);
    p1.x = __float2half_rn(o4.z); p1.y = __float2half_rn(o4.w);
    __half2* ph=(__half2*)(YH+(ll)row*DMODEL);
    ph[2*tid]=p0; ph[2*tid+1]=p1;
}
__global__ void router_kernel(const float* __restrict__ h, const float* __restrict__ Wr, const float* __restrict__ bias){
    int warp = (blockIdx.x*blockDim.x+threadIdx.x)>>5, lane = threadIdx.x&31;
    if (warp >= N_TOK) return;
    const float* hr = h + (ll)warp*DMODEL;
    float acc[NEXP];
    #pragma unroll
    for (int e=0;e<NEXP;e++) acc[e]=0.f;
    for (int d=lane; d<DMODEL; d+=32){
        float hv = hr[d];
        #pragma unroll
        for (int e=0;e<NEXP;e++) acc[e] += hv*Wr[e*DMODEL+d];
    }
    #pragma unroll
    for (int e=0;e<NEXP;e++)
        for (int o=16;o;o>>=1) acc[e] += __shfl_xor_sync(~0u, acc[e], o);
    if (lane==0){
        float b0=-1e30f,b1=-1e30f; int i0=0,i1=0;
        #pragma unroll
        for (int e=0;e<NEXP;e++){
            float v = acc[e]+bias[e];
            if (v>b0){ b1=b0;i1=i0;b0=v;i0=e; } else if (v>b1){ b1=v;i1=e; }
        }
        float m=fmaxf(acc[i0],acc[i1]);
        float e0=expf(acc[i0]-m), e1=expf(acc[i1]-m), inv=1.f/(e0+e1);
        g_topidx[2*warp]=i0; g_topidx[2*warp+1]=i1;
        g_topgate[2*warp]=e0*inv; g_topgate[2*warp+1]=e1*inv;
        atomicAdd(&g_cnt[i0],1); atomicAdd(&g_cnt[i1],1);
    }
}

// ---------- bf16 3-pass dense GEMM (in-proj; protects router precision) ----------
__global__ __launch_bounds__(256) void mm_bf(
    const bf* __restrict__ Ah, const bf* __restrict__ Al,
    const bf* __restrict__ B0h, const bf* __restrict__ B0l,
    float* __restrict__ C, int Mdense, int K, int Ncols)
{
    extern __shared__ char dsm[];
    int Mloc = Mdense;
    int bm = blockIdx.x*128; if (bm >= Mloc) return;
    int bn = blockIdx.y*128;
    unsigned sb = su32(dsm);
    int tid = threadIdx.x;
    int aslot = tid&7, arow0 = tid>>3;
    int w = tid>>5, lane = tid&31;
    int wm = (w>>2)*64, wn = (w&3)*32;
    float acc[4][4][4];
    #pragma unroll
    for (int i=0;i<4;i++)
        #pragma unroll
        for (int j=0;j<4;j++)
            #pragma unroll
            for (int q=0;q<4;q++) acc[i][j][q] = 0.f;

    int total = K>>6;
    for (int c = -1; c < total; ++c){
        int nl = c+1;
        if (nl < total){
            unsigned base = sb + (unsigned)(nl&1)*STAGE;
            int ke = nl*64 + aslot*8;
            #pragma unroll
            for (int j=0;j<4;j++){
                int r = arow0 + 32*j;
                unsigned sw = swz((unsigned)(r*128 + aslot*16));
                int ar = bm + r;
                cp16(base+sw,        Ah + (ll)ar*K + ke);
                cp16(base+16384u+sw, Al + (ll)ar*K + ke);
                int br = bn + r;
                cp16(base+32768u+sw, B0h + (ll)br*K + ke);
                cp16(base+49152u+sw, B0l + (ll)br*K + ke);
            }
            asm volatile("cp.async.commit_group;":::"memory");
        }
        if (c < 0) continue;
        if (nl < total) asm volatile("cp.async.wait_group 1;":::"memory");
        else            asm volatile("cp.async.wait_group 0;":::"memory");
        __syncthreads();

        unsigned base = sb + (unsigned)(c&1)*STAGE;
        int lrow8 = ((lane>>3)&1)*8 + (lane&7);
        #pragma unroll
        for (int ks=0; ks<4; ks++){
            int kb = ks*32 + (lane>>4)*16;
            unsigned BH[2][4], BL[2][4];
            #pragma unroll
            for (int t=0;t<2;t++){
                unsigned sw = swz((unsigned)((wn + t*16 + lrow8)*128 + kb));
                ldsm4(BH[t], base + 32768u + sw);
                ldsm4(BL[t], base + 49152u + sw);
            }
            #pragma unroll
            for (int tm=0;tm<4;tm++){
                unsigned ah[4], al[4];
                unsigned asw = swz((unsigned)((wm + tm*16 + lrow8)*128 + kb));
                ldsm4(ah, base + asw);
                ldsm4(al, base + 16384u + asw);
                #pragma unroll
                for (int t=0;t<2;t++){
                    int j0=2*t, j1=2*t+1;
                    mma_bf(acc[tm][j0], ah, BH[t][0], BH[t][2]);
                    mma_bf(acc[tm][j0], ah, BL[t][0], BL[t][2]);
                    mma_bf(acc[tm][j0], al, BH[t][0], BH[t][2]);
                    mma_bf(acc[tm][j1], ah, BH[t][1], BH[t][3]);
                    mma_bf(acc[tm][j1], ah, BL[t][1], BL[t][3]);
                    mma_bf(acc[tm][j1], al, BH[t][1], BH[t][3]);
                }
            }
        }
        __syncthreads();
    }
    #pragma unroll
    for (int tm=0;tm<4;tm++){
        int r = bm + wm + tm*16 + (lane>>2);
        #pragma unroll
        for (int j=0;j<4;j++){
            float* cc = acc[tm][j];
            int col = bn + wn + j*8 + (lane&3)*2;
            *(float2*)(C + (ll)r*Ncols + col) = make_float2(cc[0],cc[1]);
            *(float2*)(C + (ll)(r+8)*Ncols + col) = make_float2(cc[2],cc[3]);
        }
    }
}

// ---------- fp16 GEMM, templated: ALO = A has lo plane (2-pass), DUAL = gate+up fused ----------
template<int DUAL, int ALO, int GROUPED>
__global__ __launch_bounds__(256, 2) void mm_f16(
    const __half* __restrict__ Ah, const __half* __restrict__ Al,
    const __half* __restrict__ B0, const __half* __restrict__ B1,
    float* __restrict__ C, __half* __restrict__ TH,
    int Mdense, int K, int Ncols,
    const int* __restrict__ d_off, const int* __restrict__ pairtok, ll strideB)
{
    extern __shared__ char dsm[];
    constexpr unsigned ASZ = ALO ? 32768u : 16384u;
    constexpr unsigned STG = ASZ + 16384u;
    int rowBase = 0, Mloc = Mdense;
    const __half *b0 = B0, *b1 = B1;
    if (GROUPED){
        int e = blockIdx.z;
        rowBase = d_off[e]; Mloc = d_off[e+1]-rowBase;
        b0 += (ll)e*strideB;
        if (DUAL) b1 += (ll)e*strideB;
    }
    int bm = blockIdx.x*128; if (bm >= Mloc) return;
    int bn = blockIdx.y*(DUAL?64:128);

    unsigned sb = su32(dsm);
    int tid = threadIdx.x;
    int aslot = tid&7, arow0 = tid>>3;
    int ga[4];
    #pragma unroll
    for (int j=0;j<4;j++){
        int lr = bm + arow0 + 32*j; if (lr > Mloc-1) lr = Mloc-1;
        ga[j] = (GROUPED && DUAL) ? pairtok[rowBase+lr] : (rowBase+lr);
    }
    int w = tid>>5, lane = tid&31;
    int wm = DUAL ? (w>>1)*32 : (w>>2)*64;
    int wn = (DUAL ? (w&1) : (w&3))*32;
    constexpr int MT = DUAL ? 2 : 4;
    constexpr int NB = DUAL ? 4 : 2;

    float acc[4][4][4];   // dual: [0..1]=gate, [2..3]=up
    #pragma unroll
    for (int i=0;i<4;i++)
        #pragma unroll
        for (int j=0;j<4;j++)
            #pragma unroll
            for (int q=0;q<4;q++) acc[i][j][q] = 0.f;

    int total = K>>6;
    for (int c = -1; c < total; ++c){
        int nl = c+1;
        if (nl < total){
            unsigned base = sb + (unsigned)(nl&1)*STG;
            int ke = nl*64 + aslot*8;
            #pragma unroll
            for (int j=0;j<4;j++){
                int r = arow0 + 32*j;
                unsigned sw = swz((unsigned)(r*128 + aslot*16));
                cp16(base+sw, Ah + (ll)ga[j]*K + ke);
                if (ALO) cp16(base+16384u+sw, Al + (ll)ga[j]*K + ke);
                const __half* bp; int br;
                if (DUAL && r >= 64){ bp = b1; br = bn + r - 64; }
                else                { bp = b0; br = bn + r; }
                cp16(base+ASZ+sw, bp + (ll)br*K + ke);
            }
            asm volatile("cp.async.commit_group;":::"memory");
        }
        if (c < 0) continue;
        if (nl < total) asm volatile("cp.async.wait_group 1;":::"memory");
        else            asm volatile("cp.async.wait_group 0;":::"memory");
        __syncthreads();

        unsigned base = sb + (unsigned)(c&1)*STG;
        int lrow8 = ((lane>>3)&1)*8 + (lane&7);
        #pragma unroll
        for (int ks=0; ks<4; ks++){
            int kb = ks*32 + (lane>>4)*16;
            unsigned BH[NB][4];
            #pragma unroll
            for (int t=0;t<NB;t++){
                int nb = (DUAL && t>=2) ? (64 + wn + (t-2)*16) : (wn + t*16);
                ldsm4(BH[t], base + ASZ + swz((unsigned)((nb + lrow8)*128 + kb)));
            }
            #pragma unroll
            for (int tm=0;tm<MT;tm++){
                unsigned ah[4], al[4];
                unsigned asw = swz((unsigned)((wm + tm*16 + lrow8)*128 + kb));
                ldsm4(ah, base + asw);
                if (ALO) ldsm4(al, base + 16384u + asw);
                #pragma unroll
                for (int t=0;t<2;t++){
                    int j0=2*t, j1=2*t+1;
                    mma_hf(acc[tm][j0], ah, BH[t][0], BH[t][2]);
                    mma_hf(acc[tm][j1], ah, BH[t][1], BH[t][3]);
                    if (ALO){
                        mma_hf(acc[tm][j0], al, BH[t][0], BH[t][2]);
                        mma_hf(acc[tm][j1], al, BH[t][1], BH[t][3]);
                    }
                    if (DUAL){
                        mma_hf(acc[2+tm][j0], ah, BH[2+t][0], BH[2+t][2]);
                        mma_hf(acc[2+tm][j1], ah, BH[2+t][1], BH[2+t][3]);
                        if (ALO){
                            mma_hf(acc[2+tm][j0], al, BH[2+t][0], BH[2+t][2]);
                            mma_hf(acc[2+tm][j1], al, BH[2+t][1], BH[2+t][3]);
                        }
                    }
                }
            }
        }
        __syncthreads();
    }

    if (!DUAL){
        #pragma unroll
        for (int tm=0;tm<4;tm++){
            int r = bm + wm + tm*16 + (lane>>2);
            #pragma unroll
            for (int j=0;j<4;j++){
                float* cc = acc[tm][j];
                int col = bn + wn + j*8 + (lane&3)*2;
                if (r < Mloc)
                    *(float2*)(C + (ll)(rowBase+r)*Ncols + col) = make_float2(cc[0],cc[1]);
                if (r+8 < Mloc)
                    *(float2*)(C + (ll)(rowBase+r+8)*Ncols + col) = make_float2(cc[2],cc[3]);
            }
        }
    } else {
        #pragma unroll
        for (int tm=0;tm<2;tm++){
            int r = bm + wm + tm*16 + (lane>>2);
            #pragma unroll
            for (int j=0;j<4;j++){
                float* gg = acc[tm][j];
                float* uu = acc[2+tm][j];
                float v0 = gg[0]*uu[0]/(1.f+__expf(-gg[0]));
                float v1 = gg[1]*uu[1]/(1.f+__expf(-gg[1]));
                float v2 = gg[2]*uu[2]/(1.f+__expf(-gg[2]));
                float v3 = gg[3]*uu[3]/(1.f+__expf(-gg[3]));
                int col = bn + wn + j*8 + (lane&3)*2;
                __half2 h0, h1;
                h0.x = __float2half_rn(v0); h0.y = __float2half_rn(v1);
                h1.x = __float2half_rn(v2); h1.y = __float2half_rn(v3);
                if (r < Mloc)
                    *(__half2*)(TH + (ll)(rowBase+r)*Ncols + col) = h0;
                if (r+8 < Mloc)
                    *(__half2*)(TH + (ll)(rowBase+r+8)*Ncols + col) = h1;
            }
        }
    }
}

__global__ void combine_rows(const float* __restrict__ enorm, const float* __restrict__ outnorm){
    int t = blockIdx.x, tid = threadIdx.x;
    int s0=g_slotof[2*t], s1=g_slotof[2*t+1], e0=g_topidx[2*t], e1=g_topidx[2*t+1];
    float gg0=g_topgate[2*t], gg1=g_topgate[2*t+1];
    float4 a = ((const float4*)(g_Oe+(ll)s0*DMODEL))[tid];
    float4 b = ((const float4*)(g_Oe+(ll)s1*DMODEL))[tid];
    float ssa=a.x*a.x+a.y*a.y+a.z*a.z+a.w*a.w, ssb=b.x*b.x+b.y*b.y+b.z*b.z+b.w*b.w;
    __shared__ float rA[8],rB[8],rC[8];
    for (int o=16;o;o>>=1){ ssa+=__shfl_xor_sync(~0u,ssa,o); ssb+=__shfl_xor_sync(~0u,ssb,o); }
    if ((tid&31)==0){ rA[tid>>5]=ssa; rB[tid>>5]=ssb; }
    __syncthreads();
    float ta=rA[0]+rA[1]+rA[2]+rA[3]+rA[4]+rA[5]+rA[6]+rA[7];
    float tb=rB[0]+rB[1]+rB[2]+rB[3]+rB[4]+rB[5]+rB[6]+rB[7];
    float r0=rsqrtf(ta*(1.f/DMODEL)+EPSF)*gg0, r1=rsqrtf(tb*(1.f/DMODEL)+EPSF)*gg1;
    float4 w0=((const float4*)(enorm+(ll)e0*DMODEL))[tid];
    float4 w1=((const float4*)(enorm+(ll)e1*DMODEL))[tid];
    float4 c = make_float4(a.x*r0*w0.x+b.x*r1*w1.x, a.y*r0*w0.y+b.y*r1*w1.y,
                           a.z*r0*w0.z+b.z*r1*w1.z, a.w*r0*w0.w+b.w*r1*w1.w);
    float ssc=c.x*c.x+c.y*c.y+c.z*c.z+c.w*c.w;
    for (int o=16;o;o>>=1) ssc+=__shfl_xor_sync(~0u,ssc,o);
    if ((tid&31)==0) rC[tid>>5]=ssc;
    __syncthreads();
    float tc=rC[0]+rC[1]+rC[2]+rC[3]+rC[4]+rC[5]+rC[6]+rC[7];
    float rc=rsqrtf(tc*(1.f/DMODEL)+EPSF);
    float4 wo=((const float4*)outnorm)[tid];
    float4 o4=make_float4(c.x*rc*wo.x, c.y*rc*wo.y, c.z*rc*wo.z, c.w*rc*wo.w);
    __half2 p0,p1,q0,q1;
    split2h(o4.x,p0.x,q0.x); split2h(o4.y,p0.y,q0.y); split2h(o4.z,p1.x,q1.x); split2h(o4.w,p1.y,q1.y);
    __half2* ph=(__half2*)(g_yHf+(ll)t*DMODEL); __half2* pl=(__half2*)(g_yLf+(ll)t*DMODEL);
    ph[2*tid]=p0; ph[2*tid+1]=p1; pl[2*tid]=q0; pl[2*tid+1]=q1;
}

extern "C" void kernel_launch(void* const* d_in, const int* in_sizes, int n_in,
                              void* d_out, int out_size)
{
    const float* s          = (const float*)d_in[0];
    const float* W_in       = (const float*)d_in[1];
    const float* in_norm_w  = (const float*)d_in[2];
    const float* Wr         = (const float*)d_in[3];
    const float* expert_bias= (const float*)d_in[4];
    const float* Wg         = (const float*)d_in[5];
    const float* Wu         = (const float*)d_in[6];
    const float* Wd         = (const float*)d_in[7];
    const float* enorm_w    = (const float*)d_in[8];
    const float* out_norm_w = (const float*)d_in[9];
    const float* W_out      = (const float*)d_in[10];
    float* out = (float*)d_out;

    cudaFuncSetAttribute(mm_bf, cudaFuncAttributeMaxDynamicSharedMemorySize, SMEM_BF);
    cudaFuncSetAttribute(mm_f16<1,0,1>, cudaFuncAttributeMaxDynamicSharedMemorySize, 2*32768);
    cudaFuncSetAttribute(mm_f16<0,0,1>, cudaFuncAttributeMaxDynamicSharedMemorySize, 2*32768);
    cudaFuncSetAttribute(mm_f16<0,1,0>, cudaFuncAttributeMaxDynamicSharedMemorySize, 2*49152);

    void* p;
    #define SYM(v,T,sname) cudaGetSymbolAddress(&p,sname); T* v=(T*)p;
    SYM(h_ptr,float,g_h) SYM(Oe_ptr,float,g_Oe)
    SYM(sH,bf,g_sH) SYM(sL,bf,g_sL)
    SYM(WinH,bf,g_WinH) SYM(WinL,bf,g_WinL)
    SYM(hHf,__half,g_hHf)
    SYM(yHf,__half,g_yHf) SYM(yLf,__half,g_yLf)
    SYM(THf,__half,g_THf)
    SYM(WgF,__half,g_WgF) SYM(WuF,__half,g_WuF) SYM(WdF,__half,g_WdF) SYM(WoF,__half,g_WoF)
    SYM(off_ptr,int,g_off) SYM(ptok,int,g_pairtok)
    #undef SYM

    init_counts<<<1,32>>>();
    int nW = DMODEL*DMODEL/4, nE = NEXP*DFF*DMODEL/4;
    convert_hilo<<<(N_TOK*DMODEL/4+255)/256,256>>>(s, sH, sL, N_TOK*DMODEL/4);
    convert_hilo<<<(nW+255)/256,256>>>(W_in, WinH, WinL, nW);
    convert_f16<<<(nE+255)/256,256>>>(Wg, WgF, nE);
    convert_f16<<<(nE+255)/256,256>>>(Wu, WuF, nE);
    convert_f16<<<(nE+255)/256,256>>>(Wd, WdF, nE);
    convert_f16<<<(nW+255)/256,256>>>(W_out, WoF, nW);

    // h_pre = s @ W_in^T  (bf16 3-pass; protects router)
    mm_bf<<<dim3(N_TOK/128, DMODEL/128), 256, SMEM_BF>>>(
        sH, sL, WinH, WinL, h_ptr, N_TOK, DMODEL, DMODEL);
    rmsnorm_f16<<<N_TOK,256>>>(h_ptr, in_norm_w, h_ptr, hHf);
    router_kernel<<<(N_TOK*32)/256,256>>>(h_ptr, Wr, expert_bias);
    scan_offsets<<<1,32>>>();
    scatter_pairs<<<N_TOK/256,256>>>();

    // T = silu(h Wg^T) * (h Wu^T)  (fp16 1-pass A, single-fp16 T out)
    mm_f16<1,0,1><<<dim3(NPAIR/128, DFF/64, NEXP), 256, 2*32768>>>(
        hHf, nullptr, WgF, WuF, nullptr, THf,
        0, DMODEL, DFF, off_ptr, ptok, (ll)DFF*DMODEL);

    // Oe = T @ Wd^T  (fp16 1-pass, grouped)
    mm_f16<0,0,1><<<dim3(NPAIR/128, DMODEL/128, NEXP), 256, 2*32768>>>(
        THf, nullptr, WdF, nullptr, Oe_ptr, nullptr,
        0, DFF, DMODEL, off_ptr, nullptr, (ll)DMODEL*DFF);

    combine_rows<<<N_TOK,256>>>(enorm_w, out_norm_w);

    // out = y @ W_out^T  (fp16 2-pass, dense)
    mm_f16<0,1,0><<<dim3(N_TOK/128, DMODEL/128, 1), 256, 2*49152>>>(
        yHf, yLf, WoF, nullptr, out, nullptr,
        N_TOK, DMODEL, DMODEL, nullptr, nullptr, 0);
}

// round 11
// speedup vs baseline: 1.7108x; 1.0414x over previous
#include <cuda_runtime.h>
#include <cuda_bf16.h>
#include <cuda_fp16.h>

#define N_TOK 8192
#define DMODEL 1024
#define DFF 4096
#define NEXP 8
#define NPAIR (N_TOK * 2)
#define EPSF 1.1920928955078125e-07f
#define STAGE_BF 65536u
#define SMEM_BF (3 * 65536)
#define STAGE_HF 32768u
#define SMEM_HF (3 * 32768)
typedef __nv_bfloat16 bf;
typedef __nv_bfloat162 bf2;
typedef long long ll;

__device__ float g_h[(size_t)N_TOK * DMODEL];
__device__ float g_Oe[(size_t)NPAIR * DMODEL];
__device__ bf g_sH[(size_t)N_TOK*DMODEL], g_sL[(size_t)N_TOK*DMODEL];
__device__ bf g_WinH[(size_t)DMODEL*DMODEL], g_WinL[(size_t)DMODEL*DMODEL];
__device__ __half g_hHf[(size_t)N_TOK*DMODEL];
__device__ __half g_yHf[(size_t)N_TOK*DMODEL];
__device__ __half g_THf[(size_t)NPAIR*DFF];
__device__ __half g_WgF[(size_t)NEXP*DFF*DMODEL];
__device__ __half g_WuF[(size_t)NEXP*DFF*DMODEL];
__device__ __half g_WdF[(size_t)NEXP*DMODEL*DFF];
__device__ __half g_WoF[(size_t)DMODEL*DMODEL];
__device__ int g_cnt[NEXP], g_off[NEXP+1], g_cur[NEXP];
__device__ int g_pairtok[NPAIR], g_slotof[NPAIR], g_topidx[NPAIR];
__device__ float g_topgate[NPAIR];

__device__ __forceinline__ unsigned su32(const void* p){
    unsigned a; asm("{ .reg .u64 t; cvta.to.shared.u64 t, %1; cvt.u32.u64 %0, t; }":"=r"(a):"l"(p)); return a;
}
__device__ __forceinline__ void cp16(unsigned d, const void* s){
    asm volatile("cp.async.cg.shared.global [%0], [%1], 16;"::"r"(d),"l"(s));
}
__device__ __forceinline__ unsigned swz(unsigned off){ return off ^ ((off>>3)&0x70u); }
__device__ __forceinline__ void ldsm4(unsigned* r, unsigned a){
    asm volatile("ldmatrix.sync.aligned.m8n8.x4.shared.b16 {%0,%1,%2,%3}, [%4];"
        :"=r"(r[0]),"=r"(r[1]),"=r"(r[2]),"=r"(r[3]):"r"(a));
}
__device__ __forceinline__ void mma_bf(float* c, const unsigned* a, unsigned b0, unsigned b1){
    asm volatile("mma.sync.aligned.m16n8k16.row.col.f32.bf16.bf16.f32 "
        "{%0,%1,%2,%3},{%4,%5,%6,%7},{%8,%9},{%0,%1,%2,%3};"
        :"+f"(c[0]),"+f"(c[1]),"+f"(c[2]),"+f"(c[3])
        :"r"(a[0]),"r"(a[1]),"r"(a[2]),"r"(a[3]),"r"(b0),"r"(b1));
}
__device__ __forceinline__ void mma_hf(float* c, const unsigned* a, unsigned b0, unsigned b1){
    asm volatile("mma.sync.aligned.m16n8k16.row.col.f32.f16.f16.f32 "
        "{%0,%1,%2,%3},{%4,%5,%6,%7},{%8,%9},{%0,%1,%2,%3};"
        :"+f"(c[0]),"+f"(c[1]),"+f"(c[2]),"+f"(c[3])
        :"r"(a[0]),"r"(a[1]),"r"(a[2]),"r"(a[3]),"r"(b0),"r"(b1));
}
__device__ __forceinline__ void split2(float x, bf& h, bf& l){
    h = __float2bfloat16(x); l = __float2bfloat16(x - __bfloat162float(h));
}

__global__ void init_counts(){ if (threadIdx.x < NEXP) g_cnt[threadIdx.x] = 0; }
__global__ void scan_offsets(){
    if (threadIdx.x == 0){ int s=0; for(int e=0;e<NEXP;e++){ g_off[e]=s; s+=g_cnt[e]; } g_off[NEXP]=s; }
    if (threadIdx.x < NEXP) g_cur[threadIdx.x] = 0;
}
__global__ void scatter_pairs(){
    int t = blockIdx.x*blockDim.x + threadIdx.x; if (t >= N_TOK) return;
    for (int k=0;k<2;k++){
        int e = g_topidx[2*t+k];
        int slot = g_off[e] + atomicAdd(&g_cur[e],1);
        g_pairtok[slot] = t; g_slotof[2*t+k] = slot;
    }
}
__global__ void convert_hilo(const float* __restrict__ x, bf* __restrict__ h, bf* __restrict__ l, int n4){
    int i = blockIdx.x*blockDim.x + threadIdx.x; if (i >= n4) return;
    float4 v = ((const float4*)x)[i];
    bf2 p0,p1,q0,q1;
    split2(v.x,p0.x,q0.x); split2(v.y,p0.y,q0.y); split2(v.z,p1.x,q1.x); split2(v.w,p1.y,q1.y);
    ((bf2*)h)[2*i]=p0; ((bf2*)h)[2*i+1]=p1; ((bf2*)l)[2*i]=q0; ((bf2*)l)[2*i+1]=q1;
}
__global__ void convert_f16(const float* __restrict__ x, __half* __restrict__ o, int n4){
    int i = blockIdx.x*blockDim.x + threadIdx.x; if (i >= n4) return;
    float4 v = ((const float4*)x)[i];
    __half2 p0, p1;
    p0.x = __float2half_rn(v.x); p0.y = __float2half_rn(v.y);
    p1.x = __float2half_rn(v.z); p1.y = __float2half_rn(v.w);
    ((__half2*)o)[2*i]=p0; ((__half2*)o)[2*i+1]=p1;
}
__global__ void rmsnorm_f16(const float* __restrict__ X, const float* __restrict__ w,
                            float* __restrict__ Y, __half* __restrict__ YH){
    int row = blockIdx.x, tid = threadIdx.x;
    float4 v = ((const float4*)(X + (ll)row*DMODEL))[tid];
    float ss = v.x*v.x+v.y*v.y+v.z*v.z+v.w*v.w;
    __shared__ float red[8];
    for (int o=16;o;o>>=1) ss += __shfl_xor_sync(~0u, ss, o);
    if ((tid&31)==0) red[tid>>5]=ss;
    __syncthreads();
    float tot = red[0]+red[1]+red[2]+red[3]+red[4]+red[5]+red[6]+red[7];
    float r = rsqrtf(tot*(1.0f/DMODEL)+EPSF);
    float4 wv = ((const float4*)w)[tid];
    float4 o4 = make_float4(v.x*r*wv.x, v.y*r*wv.y, v.z*r*wv.z, v.w*r*wv.w);
    ((float4*)(Y + (ll)row*DMODEL))[tid] = o4;
    __half2 p0,p1;
    p0.x = __float2half_rn(o4.x); p0.y = __float2half_rn(o4.y);
    p1.x = __float2half_rn(o4.z); p1.y = __float2half_rn(o4.w);
    __half2* ph=(__half2*)(YH+(ll)row*DMODEL);
    ph[2*tid]=p0; ph[2*tid+1]=p1;
}
__global__ void router_kernel(const float* __restrict__ h, const float* __restrict__ Wr, const float* __restrict__ bias){
    int warp = (blockIdx.x*blockDim.x+threadIdx.x)>>5, lane = threadIdx.x&31;
    if (warp >= N_TOK) return;
    const float* hr = h + (ll)warp*DMODEL;
    float acc[NEXP];
    #pragma unroll
    for (int e=0;e<NEXP;e++) acc[e]=0.f;
    for (int d=lane; d<DMODEL; d+=32){
        float hv = hr[d];
        #pragma unroll
        for (int e=0;e<NEXP;e++) acc[e] += hv*Wr[e*DMODEL+d];
    }
    #pragma unroll
    for (int e=0;e<NEXP;e++)
        for (int o=16;o;o>>=1) acc[e] += __shfl_xor_sync(~0u, acc[e], o);
    if (lane==0){
        float b0=-1e30f,b1=-1e30f; int i0=0,i1=0;
        #pragma unroll
        for (int e=0;e<NEXP;e++){
            float v = acc[e]+bias[e];
            if (v>b0){ b1=b0;i1=i0;b0=v;i0=e; } else if (v>b1){ b1=v;i1=e; }
        }
        float m=fmaxf(acc[i0],acc[i1]);
        float e0=expf(acc[i0]-m), e1=expf(acc[i1]-m), inv=1.f/(e0+e1);
        g_topidx[2*warp]=i0; g_topidx[2*warp+1]=i1;
        g_topgate[2*warp]=e0*inv; g_topgate[2*warp+1]=e1*inv;
        atomicAdd(&g_cnt[i0],1); atomicAdd(&g_cnt[i1],1);
    }
}

// ---------- bf16 3-pass dense GEMM (in-proj; protects router), 3-stage pipeline ----------
__global__ __launch_bounds__(256) void mm_bf(
    const bf* __restrict__ Ah, const bf* __restrict__ Al,
    const bf* __restrict__ B0h, const bf* __restrict__ B0l,
    float* __restrict__ C, int Mdense, int K, int Ncols)
{
    extern __shared__ char dsm[];
    int Mloc = Mdense;
    int bm = blockIdx.x*128; if (bm >= Mloc) return;
    int bn = blockIdx.y*128;
    unsigned sb = su32(dsm);
    int tid = threadIdx.x;
    int aslot = tid&7, arow0 = tid>>3;
    int w = tid>>5, lane = tid&31;
    int wm = (w>>2)*64, wn = (w&3)*32;
    float acc[4][4][4];
    #pragma unroll
    for (int i=0;i<4;i++)
        #pragma unroll
        for (int j=0;j<4;j++)
            #pragma unroll
            for (int q=0;q<4;q++) acc[i][j][q] = 0.f;

    int total = K>>6;
    auto load = [&](int kt){
        unsigned base = sb + (unsigned)(kt%3)*STAGE_BF;
        int ke = kt*64 + aslot*8;
        #pragma unroll
        for (int j=0;j<4;j++){
            int r = arow0 + 32*j;
            unsigned sw = swz((unsigned)(r*128 + aslot*16));
            int ar = bm + r;
            cp16(base+sw,        Ah + (ll)ar*K + ke);
            cp16(base+16384u+sw, Al + (ll)ar*K + ke);
            int br = bn + r;
            cp16(base+32768u+sw, B0h + (ll)br*K + ke);
            cp16(base+49152u+sw, B0l + (ll)br*K + ke);
        }
        asm volatile("cp.async.commit_group;":::"memory");
    };
    if (0 < total) load(0);
    if (1 < total) load(1);
    for (int c = 0; c < total; ++c){
        if (c+2 < total) load(c+2);
        if (c+2 < total)      asm volatile("cp.async.wait_group 2;":::"memory");
        else if (c+1 < total) asm volatile("cp.async.wait_group 1;":::"memory");
        else                  asm volatile("cp.async.wait_group 0;":::"memory");
        __syncthreads();

        unsigned base = sb + (unsigned)(c%3)*STAGE_BF;
        int lrow8 = ((lane>>3)&1)*8 + (lane&7);
        #pragma unroll
        for (int ks=0; ks<4; ks++){
            int kb = ks*32 + (lane>>4)*16;
            unsigned BH[2][4], BL[2][4];
            #pragma unroll
            for (int t=0;t<2;t++){
                unsigned sw = swz((unsigned)((wn + t*16 + lrow8)*128 + kb));
                ldsm4(BH[t], base + 32768u + sw);
                ldsm4(BL[t], base + 49152u + sw);
            }
            #pragma unroll
            for (int tm=0;tm<4;tm++){
                unsigned ah[4], al[4];
                unsigned asw = swz((unsigned)((wm + tm*16 + lrow8)*128 + kb));
                ldsm4(ah, base + asw);
                ldsm4(al, base + 16384u + asw);
                #pragma unroll
                for (int t=0;t<2;t++){
                    int j0=2*t, j1=2*t+1;
                    mma_bf(acc[tm][j0], ah, BH[t][0], BH[t][2]);
                    mma_bf(acc[tm][j0], ah, BL[t][0], BL[t][2]);
                    mma_bf(acc[tm][j0], al, BH[t][0], BH[t][2]);
                    mma_bf(acc[tm][j1], ah, BH[t][1], BH[t][3]);
                    mma_bf(acc[tm][j1], ah, BL[t][1], BL[t][3]);
                    mma_bf(acc[tm][j1], al, BH[t][1], BH[t][3]);
                }
            }
        }
        __syncthreads();
    }
    #pragma unroll
    for (int tm=0;tm<4;tm++){
        int r = bm + wm + tm*16 + (lane>>2);
        #pragma unroll
        for (int j=0;j<4;j++){
            float* cc = acc[tm][j];
            int col = bn + wn + j*8 + (lane&3)*2;
            *(float2*)(C + (ll)r*Ncols + col) = make_float2(cc[0],cc[1]);
            *(float2*)(C + (ll)(r+8)*Ncols + col) = make_float2(cc[2],cc[3]);
        }
    }
}

// ---------- fp16 1-pass GEMM, 3-stage pipeline, flattened grouped grid ----------
// DUAL=1: B = 64 gate + 64 up rows, epilogue silu(g)*u -> single fp16 TH.
// GROUPED=1: blockIdx.x scans d_off to find (expert, m-tile).
template<int DUAL, int GROUPED>
__global__ __launch_bounds__(256, 2) void mm_f16(
    const __half* __restrict__ Ah,
    const __half* __restrict__ B0, const __half* __restrict__ B1,
    float* __restrict__ C, __half* __restrict__ TH,
    int Mdense, int K, int Ncols,
    const int* __restrict__ d_off, const int* __restrict__ pairtok, ll strideB)
{
    extern __shared__ char dsm[];
    int rowBase = 0, Mloc = Mdense, bm;
    const __half *b0 = B0, *b1 = B1;
    if (GROUPED){
        int idx = blockIdx.x, e = 0;
        int base0 = 0, m = 0;
        #pragma unroll 1
        for (; e < NEXP; e++){
            base0 = d_off[e]; m = d_off[e+1]-base0;
            int nt = (m+127)>>7;
            if (idx < nt) break;
            idx -= nt;
        }
        if (e == NEXP) return;
        rowBase = base0; Mloc = m; bm = idx*128;
        b0 += (ll)e*strideB;
        if (DUAL) b1 += (ll)e*strideB;
    } else {
        bm = blockIdx.x*128;
        if (bm >= Mloc) return;
    }
    int bn = blockIdx.y*(DUAL?64:128);

    unsigned sb = su32(dsm);
    int tid = threadIdx.x;
    int aslot = tid&7, arow0 = tid>>3;
    int ga[4];
    #pragma unroll
    for (int j=0;j<4;j++){
        int lr = bm + arow0 + 32*j; if (lr > Mloc-1) lr = Mloc-1;
        ga[j] = (GROUPED && DUAL) ? pairtok[rowBase+lr] : (rowBase+lr);
    }
    int w = tid>>5, lane = tid&31;
    int wm = DUAL ? (w>>1)*32 : (w>>2)*64;
    int wn = (DUAL ? (w&1) : (w&3))*32;
    constexpr int MT = DUAL ? 2 : 4;
    constexpr int NB = DUAL ? 4 : 2;

    float acc[4][4][4];   // dual: [0..1]=gate, [2..3]=up
    #pragma unroll
    for (int i=0;i<4;i++)
        #pragma unroll
        for (int j=0;j<4;j++)
            #pragma unroll
            for (int q=0;q<4;q++) acc[i][j][q] = 0.f;

    int total = K>>6;
    auto load = [&](int kt){
        unsigned base = sb + (unsigned)(kt%3)*STAGE_HF;
        int ke = kt*64 + aslot*8;
        #pragma unroll
        for (int j=0;j<4;j++){
            int r = arow0 + 32*j;
            unsigned sw = swz((unsigned)(r*128 + aslot*16));
            cp16(base+sw, Ah + (ll)ga[j]*K + ke);
            const __half* bp; int br;
            if (DUAL && r >= 64){ bp = b1; br = bn + r - 64; }
            else                { bp = b0; br = bn + r; }
            cp16(base+16384u+sw, bp + (ll)br*K + ke);
        }
        asm volatile("cp.async.commit_group;":::"memory");
    };
    if (0 < total) load(0);
    if (1 < total) load(1);
    for (int c = 0; c < total; ++c){
        if (c+2 < total) load(c+2);
        if (c+2 < total)      asm volatile("cp.async.wait_group 2;":::"memory");
        else if (c+1 < total) asm volatile("cp.async.wait_group 1;":::"memory");
        else                  asm volatile("cp.async.wait_group 0;":::"memory");
        __syncthreads();

        unsigned base = sb + (unsigned)(c%3)*STAGE_HF;
        int lrow8 = ((lane>>3)&1)*8 + (lane&7);
        #pragma unroll
        for (int ks=0; ks<4; ks++){
            int kb = ks*32 + (lane>>4)*16;
            unsigned BH[NB][4];
            #pragma unroll
            for (int t=0;t<NB;t++){
                int nb = (DUAL && t>=2) ? (64 + wn + (t-2)*16) : (wn + t*16);
                ldsm4(BH[t], base + 16384u + swz((unsigned)((nb + lrow8)*128 + kb)));
            }
            #pragma unroll
            for (int tm=0;tm<MT;tm++){
                unsigned ah[4];
                unsigned asw = swz((unsigned)((wm + tm*16 + lrow8)*128 + kb));
                ldsm4(ah, base + asw);
                #pragma unroll
                for (int t=0;t<2;t++){
                    int j0=2*t, j1=2*t+1;
                    mma_hf(acc[tm][j0], ah, BH[t][0], BH[t][2]);
                    mma_hf(acc[tm][j1], ah, BH[t][1], BH[t][3]);
                    if (DUAL){
                        mma_hf(acc[2+tm][j0], ah, BH[2+t][0], BH[2+t][2]);
                        mma_hf(acc[2+tm][j1], ah, BH[2+t][1], BH[2+t][3]);
                    }
                }
            }
        }
        __syncthreads();
    }

    if (!DUAL){
        #pragma unroll
        for (int tm=0;tm<4;tm++){
            int r = bm + wm + tm*16 + (lane>>2);
            #pragma unroll
            for (int j=0;j<4;j++){
                float* cc = acc[tm][j];
                int col = bn + wn + j*8 + (lane&3)*2;
                if (r < Mloc)
                    *(float2*)(C + (ll)(rowBase+r)*Ncols + col) = make_float2(cc[0],cc[1]);
                if (r+8 < Mloc)
                    *(float2*)(C + (ll)(rowBase+r+8)*Ncols + col) = make_float2(cc[2],cc[3]);
            }
        }
    } else {
        #pragma unroll
        for (int tm=0;tm<2;tm++){
            int r = bm + wm + tm*16 + (lane>>2);
            #pragma unroll
            for (int j=0;j<4;j++){
                float* gg = acc[tm][j];
                float* uu = acc[2+tm][j];
                float v0 = gg[0]*uu[0]/(1.f+__expf(-gg[0]));
                float v1 = gg[1]*uu[1]/(1.f+__expf(-gg[1]));
                float v2 = gg[2]*uu[2]/(1.f+__expf(-gg[2]));
                float v3 = gg[3]*uu[3]/(1.f+__expf(-gg[3]));
                int col = bn + wn + j*8 + (lane&3)*2;
                __half2 h0, h1;
                h0.x = __float2half_rn(v0); h0.y = __float2half_rn(v1);
                h1.x = __float2half_rn(v2); h1.y = __float2half_rn(v3);
                if (r < Mloc)
                    *(__half2*)(TH + (ll)(rowBase+r)*Ncols + col) = h0;
                if (r+8 < Mloc)
                    *(__half2*)(TH + (ll)(rowBase+r+8)*Ncols + col) = h1;
            }
        }
    }
}

__global__ void combine_rows(const float* __restrict__ enorm, const float* __restrict__ outnorm){
    int t = blockIdx.x, tid = threadIdx.x;
    int s0=g_slotof[2*t], s1=g_slotof[2*t+1], e0=g_topidx[2*t], e1=g_topidx[2*t+1];
    float gg0=g_topgate[2*t], gg1=g_topgate[2*t+1];
    float4 a = ((const float4*)(g_Oe+(ll)s0*DMODEL))[tid];
    float4 b = ((const float4*)(g_Oe+(ll)s1*DMODEL))[tid];
    float ssa=a.x*a.x+a.y*a.y+a.z*a.z+a.w*a.w, ssb=b.x*b.x+b.y*b.y+b.z*b.z+b.w*b.w;
    __shared__ float rA[8],rB[8],rC[8];
    for (int o=16;o;o>>=1){ ssa+=__shfl_xor_sync(~0u,ssa,o); ssb+=__shfl_xor_sync(~0u,ssb,o); }
    if ((tid&31)==0){ rA[tid>>5]=ssa; rB[tid>>5]=ssb; }
    __syncthreads();
    float ta=rA[0]+rA[1]+rA[2]+rA[3]+rA[4]+rA[5]+rA[6]+rA[7];
    float tb=rB[0]+rB[1]+rB[2]+rB[3]+rB[4]+rB[5]+rB[6]+rB[7];
    float r0=rsqrtf(ta*(1.f/DMODEL)+EPSF)*gg0, r1=rsqrtf(tb*(1.f/DMODEL)+EPSF)*gg1;
    float4 w0=((const float4*)(enorm+(ll)e0*DMODEL))[tid];
    float4 w1=((const float4*)(enorm+(ll)e1*DMODEL))[tid];
    float4 c = make_float4(a.x*r0*w0.x+b.x*r1*w1.x, a.y*r0*w0.y+b.y*r1*w1.y,
                           a.z*r0*w0.z+b.z*r1*w1.z, a.w*r0*w0.w+b.w*r1*w1.w);
    float ssc=c.x*c.x+c.y*c.y+c.z*c.z+c.w*c.w;
    for (int o=16;o;o>>=1) ssc+=__shfl_xor_sync(~0u,ssc,o);
    if ((tid&31)==0) rC[tid>>5]=ssc;
    __syncthreads();
    float tc=rC[0]+rC[1]+rC[2]+rC[3]+rC[4]+rC[5]+rC[6]+rC[7];
    float rc=rsqrtf(tc*(1.f/DMODEL)+EPSF);
    float4 wo=((const float4*)outnorm)[tid];
    float4 o4=make_float4(c.x*rc*wo.x, c.y*rc*wo.y, c.z*rc*wo.z, c.w*rc*wo.w);
    __half2 p0,p1;
    p0.x=__float2half_rn(o4.x); p0.y=__float2half_rn(o4.y);
    p1.x=__float2half_rn(o4.z); p1.y=__float2half_rn(o4.w);
    __half2* ph=(__half2*)(g_yHf+(ll)t*DMODEL);
    ph[2*tid]=p0; ph[2*tid+1]=p1;
}

extern "C" void kernel_launch(void* const* d_in, const int* in_sizes, int n_in,
                              void* d_out, int out_size)
{
    const float* s          = (const float*)d_in[0];
    const float* W_in       = (const float*)d_in[1];
    const float* in_norm_w  = (const float*)d_in[2];
    const float* Wr         = (const float*)d_in[3];
    const float* expert_bias= (const float*)d_in[4];
    const float* Wg         = (const float*)d_in[5];
    const float* Wu         = (const float*)d_in[6];
    const float* Wd         = (const float*)d_in[7];
    const float* enorm_w    = (const float*)d_in[8];
    const float* out_norm_w = (const float*)d_in[9];
    const float* W_out      = (const float*)d_in[10];
    float* out = (float*)d_out;

    cudaFuncSetAttribute(mm_bf, cudaFuncAttributeMaxDynamicSharedMemorySize, SMEM_BF);
    cudaFuncSetAttribute(mm_f16<1,1>, cudaFuncAttributeMaxDynamicSharedMemorySize, SMEM_HF);
    cudaFuncSetAttribute(mm_f16<0,1>, cudaFuncAttributeMaxDynamicSharedMemorySize, SMEM_HF);
    cudaFuncSetAttribute(mm_f16<0,0>, cudaFuncAttributeMaxDynamicSharedMemorySize, SMEM_HF);

    void* p;
    #define SYM(v,T,sname) cudaGetSymbolAddress(&p,sname); T* v=(T*)p;
    SYM(h_ptr,float,g_h) SYM(Oe_ptr,float,g_Oe)
    SYM(sH,bf,g_sH) SYM(sL,bf,g_sL)
    SYM(WinH,bf,g_WinH) SYM(WinL,bf,g_WinL)
    SYM(hHf,__half,g_hHf) SYM(yHf,__half,g_yHf)
    SYM(THf,__half,g_THf)
    SYM(WgF,__half,g_WgF) SYM(WuF,__half,g_WuF) SYM(WdF,__half,g_WdF) SYM(WoF,__half,g_WoF)
    SYM(off_ptr,int,g_off) SYM(ptok,int,g_pairtok)
    #undef SYM

    init_counts<<<1,32>>>();
    int nW = DMODEL*DMODEL/4, nE = NEXP*DFF*DMODEL/4;
    convert_hilo<<<(N_TOK*DMODEL/4+255)/256,256>>>(s, sH, sL, N_TOK*DMODEL/4);
    convert_hilo<<<(nW+255)/256,256>>>(W_in, WinH, WinL, nW);
    convert_f16<<<(nE+255)/256,256>>>(Wg, WgF, nE);
    convert_f16<<<(nE+255)/256,256>>>(Wu, WuF, nE);
    convert_f16<<<(nE+255)/256,256>>>(Wd, WdF, nE);
    convert_f16<<<(nW+255)/256,256>>>(W_out, WoF, nW);

    // h_pre = s @ W_in^T  (bf16 3-pass; protects router)
    mm_bf<<<dim3(N_TOK/128, DMODEL/128), 256, SMEM_BF>>>(
        sH, sL, WinH, WinL, h_ptr, N_TOK, DMODEL, DMODEL);
    rmsnorm_f16<<<N_TOK,256>>>(h_ptr, in_norm_w, h_ptr, hHf);
    router_kernel<<<(N_TOK*32)/256,256>>>(h_ptr, Wr, expert_bias);
    scan_offsets<<<1,32>>>();
    scatter_pairs<<<N_TOK/256,256>>>();

    // T = silu(h Wg^T) * (h Wu^T)  (fp16 1-pass, flattened grouped grid)
    mm_f16<1,1><<<dim3(NPAIR/128 + NEXP, DFF/64), 256, SMEM_HF>>>(
        hHf, WgF, WuF, nullptr, THf,
        0, DMODEL, DFF, off_ptr, ptok, (ll)DFF*DMODEL);

    // Oe = T @ Wd^T  (fp16 1-pass, flattened grouped grid)
    mm_f16<0,1><<<dim3(NPAIR/128 + NEXP, DMODEL/128), 256, SMEM_HF>>>(
        THf, WdF, nullptr, Oe_ptr, nullptr,
        0, DFF, DMODEL, off_ptr, nullptr, (ll)DMODEL*DFF);

    combine_rows<<<N_TOK,256>>>(enorm_w, out_norm_w);

    // out = y @ W_out^T  (fp16 1-pass, dense)
    mm_f16<0,0><<<dim3(N_TOK/128, DMODEL/128), 256, SMEM_HF>>>(
        yHf, WoF, nullptr, out, nullptr,
        N_TOK, DMODEL, DMODEL, nullptr, nullptr, 0);
}